// round 8
// baseline (speedup 1.0000x reference)
#include <cuda_runtime.h>
#include <cuda_fp16.h>
#include <math.h>
#include <stdint.h>

#define T     4096
#define H     16
#define HKV   4
#define D     128
#define HID   2048
#define QKV_N ((H + 2 * HKV) * D)   // 3072
#define QD    (H * D)               // 2048
#define KD    (HKV * D)             // 512
#define EPSV  1e-5f
#define GK    2048
#define NCHUNK (GK / 32)

// fp32 scratch
__device__ float g_qkv[T * QKV_N];

// fp16 scratch
__device__ __half g_hsf[T * HID];
__device__ __half g_wqf[QKV_N * HID];
__device__ __half g_wof[HID * QD];
__device__ __half g_qf[T * QD];
__device__ __half g_kf[T * KD];
__device__ __half g_vf[T * KD];
__device__ __half g_atf[T * QD];

// ---------------------------------------------------------------------------
// helpers (sm_80-level PTX only)
// ---------------------------------------------------------------------------
__device__ __forceinline__ uint32_t smem_u32(const void* p) {
    uint32_t a;
    asm("{ .reg .u64 t; cvta.to.shared.u64 t, %1; cvt.u32.u64 %0, t; }"
        : "=r"(a) : "l"(p));
    return a;
}
__device__ __forceinline__ void cp16(uint32_t dst, const void* src) {
    asm volatile("cp.async.cg.shared.global [%0], [%1], 16;"
                 :: "r"(dst), "l"(src));
}
__device__ __forceinline__ void ldsm4(uint32_t* r, uint32_t addr) {
    asm volatile("ldmatrix.sync.aligned.m8n8.x4.shared.b16 {%0,%1,%2,%3}, [%4];"
                 : "=r"(r[0]), "=r"(r[1]), "=r"(r[2]), "=r"(r[3]) : "r"(addr));
}
__device__ __forceinline__ void ldsm4t(uint32_t* r, uint32_t addr) {
    asm volatile("ldmatrix.sync.aligned.m8n8.x4.trans.shared.b16 {%0,%1,%2,%3}, [%4];"
                 : "=r"(r[0]), "=r"(r[1]), "=r"(r[2]), "=r"(r[3]) : "r"(addr));
}
__device__ __forceinline__ void ldsm2(uint32_t* r, uint32_t addr) {
    asm volatile("ldmatrix.sync.aligned.m8n8.x2.shared.b16 {%0,%1}, [%2];"
                 : "=r"(r[0]), "=r"(r[1]) : "r"(addr));
}
__device__ __forceinline__ void mma16816(float* c, const uint32_t* a,
                                         const uint32_t* b) {
    asm volatile(
        "mma.sync.aligned.m16n8k16.row.col.f32.f16.f16.f32 "
        "{%0,%1,%2,%3}, {%4,%5,%6,%7}, {%8,%9}, {%0,%1,%2,%3};"
        : "+f"(c[0]), "+f"(c[1]), "+f"(c[2]), "+f"(c[3])
        : "r"(a[0]), "r"(a[1]), "r"(a[2]), "r"(a[3]), "r"(b[0]), "r"(b[1]));
}
__device__ __forceinline__ uint32_t packh2(float a, float b) {
    __half2 h = __floats2half2_rn(a, b);
    return *(uint32_t*)&h;
}

// ---------------------------------------------------------------------------
// fused fp32 -> fp16 conversion for the three GEMM inputs (1 launch)
// ---------------------------------------------------------------------------
#define N_HS  (T * HID)
#define N_WQ  (QKV_N * HID)
#define N_WO  (HID * QD)

__global__ __launch_bounds__(256) void cvt_f16(const float* __restrict__ hs,
                                               const float* __restrict__ wq,
                                               const float* __restrict__ wo) {
    long idx = (long)blockIdx.x * 256 + threadIdx.x;
    const float* src;
    __half* dst;
    long off;
    if (idx < N_HS)             { src = hs; dst = g_hsf; off = idx; }
    else if (idx < N_HS + N_WQ) { src = wq; dst = g_wqf; off = idx - N_HS; }
    else                        { src = wo; dst = g_wof; off = idx - N_HS - N_WQ; }
    dst[off] = __float2half_rn(src[off]);
}

// ---------------------------------------------------------------------------
// mma.sync fp16 NT GEMM (unchanged from round 7)
// ---------------------------------------------------------------------------
#define TILE_B   (128 * 80)
#define STAGE_B  (2 * TILE_B)
#define GSMEM    (3 * STAGE_B)

__global__ __launch_bounds__(256)
void gemm_hmma(const __half* __restrict__ A,
               const __half* __restrict__ B,
               float* __restrict__ C, int N) {
    extern __shared__ char smem[];
    const uint32_t sbase = smem_u32(smem);
    const int tid  = threadIdx.x;
    const int wid  = tid >> 5;
    const int lane = tid & 31;
    const int wm   = wid & 1;
    const int wn   = wid >> 1;
    const int bm   = blockIdx.y * 128;
    const int bn   = blockIdx.x * 128;

    const __half* srcs[2] = {A + (size_t)bm * GK, B + (size_t)bn * GK};

    auto load_chunk = [&](int stage, int k0) {
        uint32_t db = sbase + stage * STAGE_B;
#pragma unroll
        for (int t = 0; t < 2; t++) {
            const __half* s = srcs[t] + k0;
#pragma unroll
            for (int i = 0; i < 2; i++) {
                int seg = i * 256 + tid;
                int row = seg >> 2, c16 = seg & 3;
                cp16(db + t * TILE_B + row * 80 + c16 * 16,
                     s + (size_t)row * GK + c16 * 8);
            }
        }
        asm volatile("cp.async.commit_group;" ::: "memory");
    };

    float acc[4][4][4];
#pragma unroll
    for (int mt = 0; mt < 4; mt++)
#pragma unroll
        for (int nt = 0; nt < 4; nt++)
#pragma unroll
            for (int r = 0; r < 4; r++) acc[mt][nt][r] = 0.0f;

    load_chunk(0, 0);
    load_chunk(1, 32);

    const int arow  = lane & 15;
    const int akoff = (lane >> 4) * 16;
    const int brow  = lane & 7;
    const int bkoff = ((lane >> 3) & 1) * 16;

    for (int i = 0; i < NCHUNK; i++) {
        if (i + 2 < NCHUNK)
            asm volatile("cp.async.wait_group 1;" ::: "memory");
        else
            asm volatile("cp.async.wait_group 0;" ::: "memory");
        __syncthreads();

        uint32_t s0 = sbase + (i % 3) * STAGE_B;
        uint32_t aB = s0, bB = s0 + TILE_B;

#pragma unroll
        for (int kk = 0; kk < 2; kk++) {
            const int kb = kk * 32;
            uint32_t af[4][4], bf[4][2];
#pragma unroll
            for (int mt = 0; mt < 4; mt++)
                ldsm4(af[mt], aB + (uint32_t)((wm * 64 + mt * 16 + arow) * 80 + kb + akoff));
#pragma unroll
            for (int nt = 0; nt < 4; nt++)
                ldsm2(bf[nt], bB + (uint32_t)((wn * 32 + nt * 8 + brow) * 80 + kb + bkoff));
#pragma unroll
            for (int mt = 0; mt < 4; mt++)
#pragma unroll
                for (int nt = 0; nt < 4; nt++)
                    mma16816(acc[mt][nt], af[mt], bf[nt]);
        }
        __syncthreads();
        if (i + 2 < NCHUNK) load_chunk((i + 2) % 3, (i + 2) * 32);
    }

#pragma unroll
    for (int mt = 0; mt < 4; mt++) {
        const int row0 = bm + wm * 64 + mt * 16 + (lane >> 2);
#pragma unroll
        for (int nt = 0; nt < 4; nt++) {
            const int col = bn + wn * 32 + nt * 8 + (lane & 3) * 2;
            *(float2*)&C[(size_t)row0 * N + col] =
                make_float2(acc[mt][nt][0], acc[mt][nt][1]);
            *(float2*)&C[(size_t)(row0 + 8) * N + col] =
                make_float2(acc[mt][nt][2], acc[mt][nt][3]);
        }
    }
}

// ---------------------------------------------------------------------------
// RoPE + RMSNorm. Only 64 distinct angles per token -> smem sincos table
// (powf/sincosf once per fi, not per element). Emits fp16 q/k/v.
// ---------------------------------------------------------------------------
__global__ __launch_bounds__(256) void rope_norm_kernel(
    const int* __restrict__ positions,
    const float* __restrict__ qnw,
    const float* __restrict__ knw) {
    const int t   = blockIdx.x;
    const int tid = threadIdx.x;
    const float pos  = (float)positions[t];
    const float qpre = 0.08838834764831845f * 1.4426950408889634f;

    __shared__ float row[QD];
    __shared__ float red[256];
    __shared__ float cs[64], sn[64];

    if (tid < 64) {
        float inv = powf(10000.0f, -(float)(2 * tid) * (1.0f / 128.0f));
        sincosf(pos * inv, &sn[tid], &cs[tid]);
    }
    __syncthreads();

    const float* base = g_qkv + (size_t)t * QKV_N;

    float ss = 0.0f;
#pragma unroll
    for (int i = 0; i < QD / 256; i++) {
        int idx = tid + i * 256;
        int d   = idx & 127;
        int hb  = idx - d;
        int fi  = d & 63;
        float cv = cs[fi], sv = sn[fi];
        float v;
        if (d < 64) v = base[hb + d] * cv - base[hb + d + 64] * sv;
        else        v = base[hb + d] * cv + base[hb + d - 64] * sv;
        row[idx] = v;
        ss += v * v;
    }
    red[tid] = ss;
    __syncthreads();
    for (int s2 = 128; s2 > 0; s2 >>= 1) {
        if (tid < s2) red[tid] += red[tid + s2];
        __syncthreads();
    }
    float qscale = rsqrtf(red[0] * (1.0f / QD) + EPSV) * qpre;
#pragma unroll
    for (int i = 0; i < QD / 256; i++) {
        int idx = tid + i * 256;
        g_qf[(size_t)t * QD + idx] = __float2half_rn(row[idx] * qscale * qnw[idx]);
    }
    __syncthreads();

    const float* kbase = base + QD;
    float ssk = 0.0f;
#pragma unroll
    for (int i = 0; i < KD / 256; i++) {
        int idx = tid + i * 256;
        int d   = idx & 127;
        int hb  = idx - d;
        int fi  = d & 63;
        float cv = cs[fi], sv = sn[fi];
        float v;
        if (d < 64) v = kbase[hb + d] * cv - kbase[hb + d + 64] * sv;
        else        v = kbase[hb + d] * cv + kbase[hb + d - 64] * sv;
        row[idx] = v;
        ssk += v * v;
    }
    red[tid] = ssk;
    __syncthreads();
    for (int s2 = 128; s2 > 0; s2 >>= 1) {
        if (tid < s2) red[tid] += red[tid + s2];
        __syncthreads();
    }
    float kscale = rsqrtf(red[0] * (1.0f / KD) + EPSV);
#pragma unroll
    for (int i = 0; i < KD / 256; i++) {
        int idx = tid + i * 256;
        g_kf[(size_t)t * KD + idx] = __float2half_rn(row[idx] * kscale * knw[idx]);
    }
    const float* vbase = base + QD + KD;
#pragma unroll
    for (int i = 0; i < KD / 256; i++) {
        int idx = tid + i * 256;
        g_vf[(size_t)t * KD + idx] = __float2half_rn(vbase[idx]);
    }
}

// ---------------------------------------------------------------------------
// flash_mma: causal GQA attention, fp16 mma.
// CTA: 64 queries x 1 head, 4 warps (16 rows each), 32-key double-buffered
// KV tiles. Small CTA -> 3 CTAs/SM (independent softmax/mma phases keep the
// tensor pipe busy). Softmax in exp2 domain (Q pre-scaled).
// ---------------------------------------------------------------------------
#define KVS     272                        // padded row stride (bytes)
#define QTILE   (64 * KVS)                 // 17408
#define KVT32   (32 * KVS)                 // 8704 (one of K or V)
#define KVSTG   (2 * KVT32)                // 17408 (K + V)
#define FSMEM   (QTILE + 2 * KVSTG)        // 52224

__global__ __launch_bounds__(128, 3) void flash_mma() {
    extern __shared__ char smem[];
    const uint32_t sbase = smem_u32(smem);
    const int tid  = threadIdx.x;
    const int wg   = tid >> 5;
    const int lane = tid & 31;
    const int h    = blockIdx.y;
    const int kvh  = h >> 2;
    const int qb   = (int)gridDim.x - 1 - (int)blockIdx.x;
    const int q0   = qb * 64;
    const int ntiles = 2 * qb + 2;         // 32-key tiles covering [0, q0+64)

    // ---- Q load ----
    {
        const __half* s0 = g_qf + (size_t)q0 * QD + h * D;
#pragma unroll
        for (int i = 0; i < 8; i++) {
            int seg = i * 128 + tid;           // 0..1023
            int row = seg >> 4, c = seg & 15;
            cp16(sbase + row * KVS + c * 16, s0 + (size_t)row * QD + c * 8);
        }
        asm volatile("cp.async.commit_group;" ::: "memory");
    }

    auto load_kv = [&](int stage, int k0) {
        const __half* srcs[2] = {g_kf + (size_t)k0 * KD + kvh * D,
                                 g_vf + (size_t)k0 * KD + kvh * D};
        uint32_t db = sbase + QTILE + stage * KVSTG;
#pragma unroll
        for (int t = 0; t < 2; t++) {
#pragma unroll
            for (int i = 0; i < 4; i++) {
                int seg = i * 128 + tid;       // 0..511
                int row = seg >> 4, c = seg & 15;
                cp16(db + t * KVT32 + row * KVS + c * 16,
                     srcs[t] + (size_t)row * KD + c * 8);
            }
        }
        asm volatile("cp.async.commit_group;" ::: "memory");
    };

    load_kv(0, 0);

    float o[16][4];
#pragma unroll
    for (int nt = 0; nt < 16; nt++)
#pragma unroll
        for (int r = 0; r < 4; r++) o[nt][r] = 0.0f;
    float m_lo = -1e30f, m_hi = -1e30f, l_lo = 0.0f, l_hi = 0.0f;

    const uint32_t q_off = (uint32_t)((wg * 16 + (lane & 15)) * KVS + (lane >> 4) * 16);
    const uint32_t k_off = (uint32_t)((((lane >> 4) << 3) + (lane & 7)) * KVS +
                                      ((lane >> 3) & 1) * 16);
    const uint32_t v_off = (uint32_t)(((((lane >> 3) & 1) << 3) + (lane & 7)) * KVS +
                                      (lane >> 4) * 16);
    const int r_lo = q0 + wg * 16 + (lane >> 2);
    const int r_hi = r_lo + 8;

    for (int it = 0; it < ntiles; it++) {
        const int k0 = it * 32;
        if (it + 1 < ntiles) {
            load_kv((it + 1) & 1, (it + 1) * 32);
            asm volatile("cp.async.wait_group 1;" ::: "memory");
        } else {
            asm volatile("cp.async.wait_group 0;" ::: "memory");
        }
        __syncthreads();

        if (k0 <= q0 + wg * 16 + 15) {        // warp not fully masked
            const uint32_t kb = sbase + QTILE + (it & 1) * KVSTG;

            // ---- S = Q K^T ----
            float s[4][4];
#pragma unroll
            for (int nt = 0; nt < 4; nt++)
#pragma unroll
                for (int r = 0; r < 4; r++) s[nt][r] = 0.0f;

#pragma unroll
            for (int kk = 0; kk < 8; kk++) {
                uint32_t af[4];
                ldsm4(af, sbase + q_off + kk * 32);
#pragma unroll
                for (int np = 0; np < 2; np++) {
                    uint32_t bf[4];
                    ldsm4(bf, kb + k_off + np * 16 * KVS + kk * 32);
                    mma16816(s[2 * np],     af, &bf[0]);
                    mma16816(s[2 * np + 1], af, &bf[2]);
                }
            }

            // ---- causal mask (diagonal region only) ----
            if (k0 + 31 > q0 + wg * 16) {
#pragma unroll
                for (int nt = 0; nt < 4; nt++) {
#pragma unroll
                    for (int c = 0; c < 2; c++) {
                        int key = k0 + nt * 8 + (lane & 3) * 2 + c;
                        if (key > r_lo) s[nt][c]     = -1e30f;
                        if (key > r_hi) s[nt][2 + c] = -1e30f;
                    }
                }
            }

            // ---- online softmax (exp2 domain) ----
            float mx_lo = fmaxf(fmaxf(s[0][0], s[0][1]), fmaxf(s[1][0], s[1][1]));
            float mx_hi = fmaxf(fmaxf(s[0][2], s[0][3]), fmaxf(s[1][2], s[1][3]));
            mx_lo = fmaxf(mx_lo, fmaxf(fmaxf(s[2][0], s[2][1]), fmaxf(s[3][0], s[3][1])));
            mx_hi = fmaxf(mx_hi, fmaxf(fmaxf(s[2][2], s[2][3]), fmaxf(s[3][2], s[3][3])));
            mx_lo = fmaxf(mx_lo, __shfl_xor_sync(0xffffffffu, mx_lo, 1));
            mx_lo = fmaxf(mx_lo, __shfl_xor_sync(0xffffffffu, mx_lo, 2));
            mx_hi = fmaxf(mx_hi, __shfl_xor_sync(0xffffffffu, mx_hi, 1));
            mx_hi = fmaxf(mx_hi, __shfl_xor_sync(0xffffffffu, mx_hi, 2));
            float mn_lo = fmaxf(m_lo, mx_lo);
            float mn_hi = fmaxf(m_hi, mx_hi);
            float cr_lo = exp2f(m_lo - mn_lo);
            float cr_hi = exp2f(m_hi - mn_hi);
            m_lo = mn_lo; m_hi = mn_hi;

            uint32_t p2[4][2];
            float sum_lo = 0.0f, sum_hi = 0.0f;
#pragma unroll
            for (int nt = 0; nt < 4; nt++) {
                float p0 = exp2f(s[nt][0] - m_lo);
                float p1 = exp2f(s[nt][1] - m_lo);
                float pc = exp2f(s[nt][2] - m_hi);
                float p3 = exp2f(s[nt][3] - m_hi);
                sum_lo += p0 + p1;
                sum_hi += pc + p3;
                p2[nt][0] = packh2(p0, p1);
                p2[nt][1] = packh2(pc, p3);
            }
            sum_lo += __shfl_xor_sync(0xffffffffu, sum_lo, 1);
            sum_lo += __shfl_xor_sync(0xffffffffu, sum_lo, 2);
            sum_hi += __shfl_xor_sync(0xffffffffu, sum_hi, 1);
            sum_hi += __shfl_xor_sync(0xffffffffu, sum_hi, 2);
            l_lo = l_lo * cr_lo + sum_lo;
            l_hi = l_hi * cr_hi + sum_hi;
#pragma unroll
            for (int nt = 0; nt < 16; nt++) {
                o[nt][0] *= cr_lo; o[nt][1] *= cr_lo;
                o[nt][2] *= cr_hi; o[nt][3] *= cr_hi;
            }

            // ---- O += P V ----
            const uint32_t vb = kb + KVT32;
#pragma unroll
            for (int kk = 0; kk < 2; kk++) {
                uint32_t pa[4] = {p2[2 * kk][0], p2[2 * kk][1],
                                  p2[2 * kk + 1][0], p2[2 * kk + 1][1]};
#pragma unroll
                for (int nd = 0; nd < 8; nd++) {
                    uint32_t vf[4];
                    ldsm4t(vf, vb + v_off + kk * 16 * KVS + nd * 32);
                    mma16816(o[2 * nd],     pa, &vf[0]);
                    mma16816(o[2 * nd + 1], pa, &vf[2]);
                }
            }
        }
        __syncthreads();
    }

    // ---- epilogue: fp16 attn output ----
    const float inv_lo = 1.0f / l_lo;
    const float inv_hi = 1.0f / l_hi;
#pragma unroll
    for (int nt = 0; nt < 16; nt++) {
        int col = h * D + nt * 8 + (lane & 3) * 2;
        *(uint32_t*)&g_atf[(size_t)r_lo * QD + col] =
            packh2(o[nt][0] * inv_lo, o[nt][1] * inv_lo);
        *(uint32_t*)&g_atf[(size_t)r_hi * QD + col] =
            packh2(o[nt][2] * inv_hi, o[nt][3] * inv_hi);
    }
}

// ---------------------------------------------------------------------------
// Launch
// ---------------------------------------------------------------------------
extern "C" void kernel_launch(void* const* d_in, const int* in_sizes, int n_in,
                              void* d_out, int out_size) {
    const int*   positions = (const int*)d_in[0];
    const float* hs        = (const float*)d_in[1];
    const float* w_qkv     = (const float*)d_in[2];
    const float* w_o       = (const float*)d_in[3];
    const float* qnw       = (const float*)d_in[4];
    const float* knw       = (const float*)d_in[5];
    float*       out       = (float*)d_out;

    float* qkv_p;
    cudaGetSymbolAddress((void**)&qkv_p, g_qkv);

    __half *hsf, *wqf, *wof, *atf;
    cudaGetSymbolAddress((void**)&hsf, g_hsf);
    cudaGetSymbolAddress((void**)&wqf, g_wqf);
    cudaGetSymbolAddress((void**)&wof, g_wof);
    cudaGetSymbolAddress((void**)&atf, g_atf);

    static bool attr_set = false;
    if (!attr_set) {
        cudaFuncSetAttribute(gemm_hmma,
                             cudaFuncAttributeMaxDynamicSharedMemorySize, GSMEM);
        cudaFuncSetAttribute(flash_mma,
                             cudaFuncAttributeMaxDynamicSharedMemorySize, FSMEM);
        attr_set = true;
    }

    // 1) fused fp32->fp16 conversions
    cvt_f16<<<(N_HS + N_WQ + N_WO) / 256, 256>>>(hs, w_qkv, w_o);
    // 2) QKV projection
    {
        dim3 grid(QKV_N / 128, T / 128);
        gemm_hmma<<<grid, 256, GSMEM>>>(hsf, wqf, qkv_p, QKV_N);
    }
    // 3) RoPE + RMSNorm
    rope_norm_kernel<<<T, 256>>>(positions, qnw, knw);
    // 4) Causal GQA attention (4 warps/CTA, 3 CTAs/SM)
    {
        dim3 grid(T / 64, H);
        flash_mma<<<grid, 128, FSMEM>>>();
    }
    // 5) Output projection
    {
        dim3 grid(HID / 128, T / 128);
        gemm_hmma<<<grid, 256, GSMEM>>>(atf, wof, out, HID);
    }
}

// round 9
// speedup vs baseline: 1.1110x; 1.1110x over previous
#include <cuda_runtime.h>
#include <cuda_fp16.h>
#include <math.h>
#include <stdint.h>

#define T     4096
#define H     16
#define HKV   4
#define D     128
#define HID   2048
#define QKV_N ((H + 2 * HKV) * D)   // 3072
#define QD    (H * D)               // 2048
#define KD    (HKV * D)             // 512
#define EPSV  1e-5f
#define GK    2048
#define NCHUNK (GK / 32)

// fp32 scratch
__device__ float g_qkv[T * QKV_N];

// fp16 scratch
__device__ __half g_hsf[T * HID];
__device__ __half g_wqf[QKV_N * HID];
__device__ __half g_wof[HID * QD];
__device__ __half g_qf[T * QD];
__device__ __half g_kf[T * KD];
__device__ __half g_vf[T * KD];
__device__ __half g_atf[T * QD];

// ---------------------------------------------------------------------------
// helpers (sm_80-level PTX only)
// ---------------------------------------------------------------------------
__device__ __forceinline__ uint32_t smem_u32(const void* p) {
    uint32_t a;
    asm("{ .reg .u64 t; cvta.to.shared.u64 t, %1; cvt.u32.u64 %0, t; }"
        : "=r"(a) : "l"(p));
    return a;
}
__device__ __forceinline__ void cp16(uint32_t dst, const void* src) {
    asm volatile("cp.async.cg.shared.global [%0], [%1], 16;"
                 :: "r"(dst), "l"(src));
}
__device__ __forceinline__ void ldsm4(uint32_t* r, uint32_t addr) {
    asm volatile("ldmatrix.sync.aligned.m8n8.x4.shared.b16 {%0,%1,%2,%3}, [%4];"
                 : "=r"(r[0]), "=r"(r[1]), "=r"(r[2]), "=r"(r[3]) : "r"(addr));
}
__device__ __forceinline__ void ldsm4t(uint32_t* r, uint32_t addr) {
    asm volatile("ldmatrix.sync.aligned.m8n8.x4.trans.shared.b16 {%0,%1,%2,%3}, [%4];"
                 : "=r"(r[0]), "=r"(r[1]), "=r"(r[2]), "=r"(r[3]) : "r"(addr));
}
__device__ __forceinline__ void ldsm2(uint32_t* r, uint32_t addr) {
    asm volatile("ldmatrix.sync.aligned.m8n8.x2.shared.b16 {%0,%1}, [%2];"
                 : "=r"(r[0]), "=r"(r[1]) : "r"(addr));
}
__device__ __forceinline__ void mma16816(float* c, const uint32_t* a,
                                         const uint32_t* b) {
    asm volatile(
        "mma.sync.aligned.m16n8k16.row.col.f32.f16.f16.f32 "
        "{%0,%1,%2,%3}, {%4,%5,%6,%7}, {%8,%9}, {%0,%1,%2,%3};"
        : "+f"(c[0]), "+f"(c[1]), "+f"(c[2]), "+f"(c[3])
        : "r"(a[0]), "r"(a[1]), "r"(a[2]), "r"(a[3]), "r"(b[0]), "r"(b[1]));
}
__device__ __forceinline__ uint32_t packh2(float a, float b) {
    __half2 h = __floats2half2_rn(a, b);
    return *(uint32_t*)&h;
}

// ---------------------------------------------------------------------------
// fused fp32 -> fp16 conversion (vectorized, 1 launch)
// ---------------------------------------------------------------------------
#define N_HS  (T * HID)
#define N_WQ  (QKV_N * HID)
#define N_WO  (HID * QD)

__global__ __launch_bounds__(256) void cvt_f16(const float* __restrict__ hs,
                                               const float* __restrict__ wq,
                                               const float* __restrict__ wo) {
    long idx = ((long)blockIdx.x * 256 + threadIdx.x) * 4;
    const float* src;
    __half* dst;
    long off;
    if (idx < N_HS)             { src = hs; dst = g_hsf; off = idx; }
    else if (idx < N_HS + N_WQ) { src = wq; dst = g_wqf; off = idx - N_HS; }
    else                        { src = wo; dst = g_wof; off = idx - N_HS - N_WQ; }
    float4 v = *(const float4*)(src + off);
    uint2 w = make_uint2(packh2(v.x, v.y), packh2(v.z, v.w));
    *(uint2*)(dst + off) = w;
}

// ---------------------------------------------------------------------------
// mma.sync fp16 NT GEMM (unchanged)
// ---------------------------------------------------------------------------
#define TILE_B   (128 * 80)
#define STAGE_B  (2 * TILE_B)
#define GSMEM    (3 * STAGE_B)

__global__ __launch_bounds__(256)
void gemm_hmma(const __half* __restrict__ A,
               const __half* __restrict__ B,
               float* __restrict__ C, int N) {
    extern __shared__ char smem[];
    const uint32_t sbase = smem_u32(smem);
    const int tid  = threadIdx.x;
    const int wid  = tid >> 5;
    const int lane = tid & 31;
    const int wm   = wid & 1;
    const int wn   = wid >> 1;
    const int bm   = blockIdx.y * 128;
    const int bn   = blockIdx.x * 128;

    const __half* srcs[2] = {A + (size_t)bm * GK, B + (size_t)bn * GK};

    auto load_chunk = [&](int stage, int k0) {
        uint32_t db = sbase + stage * STAGE_B;
#pragma unroll
        for (int t = 0; t < 2; t++) {
            const __half* s = srcs[t] + k0;
#pragma unroll
            for (int i = 0; i < 2; i++) {
                int seg = i * 256 + tid;
                int row = seg >> 2, c16 = seg & 3;
                cp16(db + t * TILE_B + row * 80 + c16 * 16,
                     s + (size_t)row * GK + c16 * 8);
            }
        }
        asm volatile("cp.async.commit_group;" ::: "memory");
    };

    float acc[4][4][4];
#pragma unroll
    for (int mt = 0; mt < 4; mt++)
#pragma unroll
        for (int nt = 0; nt < 4; nt++)
#pragma unroll
            for (int r = 0; r < 4; r++) acc[mt][nt][r] = 0.0f;

    load_chunk(0, 0);
    load_chunk(1, 32);

    const int arow  = lane & 15;
    const int akoff = (lane >> 4) * 16;
    const int brow  = lane & 7;
    const int bkoff = ((lane >> 3) & 1) * 16;

    for (int i = 0; i < NCHUNK; i++) {
        if (i + 2 < NCHUNK)
            asm volatile("cp.async.wait_group 1;" ::: "memory");
        else
            asm volatile("cp.async.wait_group 0;" ::: "memory");
        __syncthreads();

        uint32_t s0 = sbase + (i % 3) * STAGE_B;
        uint32_t aB = s0, bB = s0 + TILE_B;

#pragma unroll
        for (int kk = 0; kk < 2; kk++) {
            const int kb = kk * 32;
            uint32_t af[4][4], bf[4][2];
#pragma unroll
            for (int mt = 0; mt < 4; mt++)
                ldsm4(af[mt], aB + (uint32_t)((wm * 64 + mt * 16 + arow) * 80 + kb + akoff));
#pragma unroll
            for (int nt = 0; nt < 4; nt++)
                ldsm2(bf[nt], bB + (uint32_t)((wn * 32 + nt * 8 + brow) * 80 + kb + bkoff));
#pragma unroll
            for (int mt = 0; mt < 4; mt++)
#pragma unroll
                for (int nt = 0; nt < 4; nt++)
                    mma16816(acc[mt][nt], af[mt], bf[nt]);
        }
        __syncthreads();
        if (i + 2 < NCHUNK) load_chunk((i + 2) % 3, (i + 2) * 32);
    }

#pragma unroll
    for (int mt = 0; mt < 4; mt++) {
        const int row0 = bm + wm * 64 + mt * 16 + (lane >> 2);
#pragma unroll
        for (int nt = 0; nt < 4; nt++) {
            const int col = bn + wn * 32 + nt * 8 + (lane & 3) * 2;
            *(float2*)&C[(size_t)row0 * N + col] =
                make_float2(acc[mt][nt][0], acc[mt][nt][1]);
            *(float2*)&C[(size_t)(row0 + 8) * N + col] =
                make_float2(acc[mt][nt][2], acc[mt][nt][3]);
        }
    }
}

// ---------------------------------------------------------------------------
// RoPE + RMSNorm, vectorized. smem sincos table (64 angles). Emits fp16.
// ---------------------------------------------------------------------------
__global__ __launch_bounds__(256) void rope_norm_kernel(
    const int* __restrict__ positions,
    const float* __restrict__ qnw,
    const float* __restrict__ knw) {
    const int t    = blockIdx.x;
    const int tid  = threadIdx.x;
    const int lane = tid & 31;
    const float pos  = (float)positions[t];
    const float qpre = 0.08838834764831845f * 1.4426950408889634f;

    __shared__ float cs[64], sn[64];
    __shared__ float red[8];

    if (tid < 64) {
        float inv = powf(10000.0f, -(float)(2 * tid) * (1.0f / 128.0f));
        sincosf(pos * inv, &sn[tid], &cs[tid]);
    }
    __syncthreads();

    const float* base = g_qkv + (size_t)t * QKV_N;

    // ---- Q: thread owns 4 rotation pairs (head, c4..c4+3 | +64) ----
    const int head = tid >> 4;
    const int c4   = (tid & 15) * 4;
    float4 a = *(const float4*)(base + head * 128 + c4);
    float4 b = *(const float4*)(base + head * 128 + 64 + c4);
    float o1[4], o2[4];
    {
        const float av[4] = {a.x, a.y, a.z, a.w};
        const float bv[4] = {b.x, b.y, b.z, b.w};
        float ss = 0.0f;
#pragma unroll
        for (int j = 0; j < 4; j++) {
            float cv = cs[c4 + j], sv = sn[c4 + j];
            o1[j] = av[j] * cv - bv[j] * sv;
            o2[j] = bv[j] * cv + av[j] * sv;
            ss += o1[j] * o1[j] + o2[j] * o2[j];
        }
#pragma unroll
        for (int off = 16; off; off >>= 1)
            ss += __shfl_xor_sync(0xffffffffu, ss, off);
        if (lane == 0) red[tid >> 5] = ss;
    }
    __syncthreads();
    {
        float tot = red[0] + red[1] + red[2] + red[3] +
                    red[4] + red[5] + red[6] + red[7];
        float qs = rsqrtf(tot * (1.0f / QD) + EPSV) * qpre;
        float4 w1 = *(const float4*)(qnw + head * 128 + c4);
        float4 w2 = *(const float4*)(qnw + head * 128 + 64 + c4);
        __half* dst = g_qf + (size_t)t * QD + head * 128 + c4;
        *(uint2*)dst = make_uint2(packh2(o1[0] * qs * w1.x, o1[1] * qs * w1.y),
                                  packh2(o1[2] * qs * w1.z, o1[3] * qs * w1.w));
        *(uint2*)(dst + 64) = make_uint2(packh2(o2[0] * qs * w2.x, o2[1] * qs * w2.y),
                                         packh2(o2[2] * qs * w2.z, o2[3] * qs * w2.w));
    }
    __syncthreads();   // red reuse

    // ---- K: thread owns 1 rotation pair ----
    const int khead = tid >> 6;
    const int fi    = tid & 63;
    const float* kp = base + QD + khead * 128 + fi;
    float k1, k2;
    {
        float ka = kp[0], kb = kp[64];
        float cv = cs[fi], sv = sn[fi];
        k1 = ka * cv - kb * sv;
        k2 = kb * cv + ka * sv;
        float ss = k1 * k1 + k2 * k2;
#pragma unroll
        for (int off = 16; off; off >>= 1)
            ss += __shfl_xor_sync(0xffffffffu, ss, off);
        if (lane == 0) red[tid >> 5] = ss;
    }
    __syncthreads();
    {
        float tot = red[0] + red[1] + red[2] + red[3] +
                    red[4] + red[5] + red[6] + red[7];
        float ks = rsqrtf(tot * (1.0f / KD) + EPSV);
        __half* dst = g_kf + (size_t)t * KD + khead * 128 + fi;
        dst[0]  = __float2half_rn(k1 * ks * knw[khead * 128 + fi]);
        dst[64] = __float2half_rn(k2 * ks * knw[khead * 128 + 64 + fi]);
    }

    // ---- V: thread owns 2 elements ----
    {
        float2 v2 = *(const float2*)(base + QD + KD + tid * 2);
        *(uint32_t*)(g_vf + (size_t)t * KD + tid * 2) = packh2(v2.x, v2.y);
    }
}

// ---------------------------------------------------------------------------
// flash_mma: causal GQA attention, fp16 mma, software-pipelined.
// CTA: 64 queries x 1 head, 4 warps (16 rows each), 64-key tiles, 2-stage KV.
// Per iter: softmax(it) -> PV(it) -> S(it+1), so softmax never waits on the
// S-MMAs it consumes (issued a full phase earlier). Q fragments in registers.
// 2 CTAs/SM. Softmax in exp2 domain (Q pre-scaled).
// ---------------------------------------------------------------------------
#define KVS     272                        // padded row stride (bytes)
#define QTILE   (64 * KVS)                 // 17408
#define KVT     (64 * KVS)                 // 17408 (one of K or V)
#define KVSTG   (2 * KVT)                  // 34816 (K + V)
#define FSMEM   (QTILE + 2 * KVSTG)        // 87040

__global__ __launch_bounds__(128, 2) void flash_mma() {
    extern __shared__ char smem[];
    const uint32_t sbase = smem_u32(smem);
    const int tid  = threadIdx.x;
    const int wg   = tid >> 5;
    const int lane = tid & 31;
    const int h    = blockIdx.y;
    const int kvh  = h >> 2;
    const int qb   = (int)gridDim.x - 1 - (int)blockIdx.x;
    const int q0   = qb * 64;
    const int nt   = qb + 1;               // 64-key tiles covering [0, q0+64)

    // ---- Q load ----
    {
        const __half* s0 = g_qf + (size_t)q0 * QD + h * D;
#pragma unroll
        for (int i = 0; i < 8; i++) {
            int seg = i * 128 + tid;           // 0..1023
            int row = seg >> 4, c = seg & 15;
            cp16(sbase + row * KVS + c * 16, s0 + (size_t)row * QD + c * 8);
        }
        asm volatile("cp.async.commit_group;" ::: "memory");
    }

    auto load_kv = [&](int stage, int k0) {
        const __half* srcs[2] = {g_kf + (size_t)k0 * KD + kvh * D,
                                 g_vf + (size_t)k0 * KD + kvh * D};
        uint32_t db = sbase + QTILE + stage * KVSTG;
#pragma unroll
        for (int t = 0; t < 2; t++) {
#pragma unroll
            for (int i = 0; i < 8; i++) {
                int seg = i * 128 + tid;       // 0..1023
                int row = seg >> 4, c = seg & 15;
                cp16(db + t * KVT + row * KVS + c * 16,
                     srcs[t] + (size_t)row * KD + c * 8);
            }
        }
        asm volatile("cp.async.commit_group;" ::: "memory");
    };

    load_kv(0, 0);
    if (nt > 1) load_kv(1, 64);

    if (nt > 1) asm volatile("cp.async.wait_group 1;" ::: "memory");
    else        asm volatile("cp.async.wait_group 0;" ::: "memory");
    __syncthreads();

    const uint32_t q_off = (uint32_t)((wg * 16 + (lane & 15)) * KVS + (lane >> 4) * 16);
    const uint32_t k_off = (uint32_t)((((lane >> 4) << 3) + (lane & 7)) * KVS +
                                      ((lane >> 3) & 1) * 16);
    const uint32_t v_off = (uint32_t)(((((lane >> 3) & 1) << 3) + (lane & 7)) * KVS +
                                      (lane >> 4) * 16);
    const int r_lo = q0 + wg * 16 + (lane >> 2);
    const int r_hi = r_lo + 8;

    // ---- hoist Q fragments to registers (reused every tile) ----
    uint32_t qf[8][4];
#pragma unroll
    for (int kk = 0; kk < 8; kk++) ldsm4(qf[kk], sbase + q_off + kk * 32);

    float o[16][4];
#pragma unroll
    for (int ntl = 0; ntl < 16; ntl++)
#pragma unroll
        for (int r = 0; r < 4; r++) o[ntl][r] = 0.0f;
    float m_lo = -1e30f, m_hi = -1e30f, l_lo = 0.0f, l_hi = 0.0f;

    float s[8][4];

    auto compute_S = [&](int stage) {
        const uint32_t kb = sbase + QTILE + stage * KVSTG;
#pragma unroll
        for (int ntl = 0; ntl < 8; ntl++)
#pragma unroll
            for (int r = 0; r < 4; r++) s[ntl][r] = 0.0f;
#pragma unroll
        for (int kk = 0; kk < 8; kk++) {
#pragma unroll
            for (int np = 0; np < 4; np++) {
                uint32_t bf[4];
                ldsm4(bf, kb + k_off + np * 16 * KVS + kk * 32);
                mma16816(s[2 * np],     qf[kk], &bf[0]);
                mma16816(s[2 * np + 1], qf[kk], &bf[2]);
            }
        }
    };

    compute_S(0);

    for (int it = 0; it < nt; it++) {
        // ---- softmax(it) (s was produced one phase ago) ----
        if (it == nt - 1) {                    // diagonal tile
#pragma unroll
            for (int ntl = 0; ntl < 8; ntl++) {
#pragma unroll
                for (int c = 0; c < 2; c++) {
                    int key = it * 64 + ntl * 8 + (lane & 3) * 2 + c;
                    if (key > r_lo) s[ntl][c]     = -1e30f;
                    if (key > r_hi) s[ntl][2 + c] = -1e30f;
                }
            }
        }
        float mx_lo = -1e30f, mx_hi = -1e30f;
#pragma unroll
        for (int ntl = 0; ntl < 8; ntl++) {
            mx_lo = fmaxf(mx_lo, fmaxf(s[ntl][0], s[ntl][1]));
            mx_hi = fmaxf(mx_hi, fmaxf(s[ntl][2], s[ntl][3]));
        }
        mx_lo = fmaxf(mx_lo, __shfl_xor_sync(0xffffffffu, mx_lo, 1));
        mx_lo = fmaxf(mx_lo, __shfl_xor_sync(0xffffffffu, mx_lo, 2));
        mx_hi = fmaxf(mx_hi, __shfl_xor_sync(0xffffffffu, mx_hi, 1));
        mx_hi = fmaxf(mx_hi, __shfl_xor_sync(0xffffffffu, mx_hi, 2));
        float mn_lo = fmaxf(m_lo, mx_lo);
        float mn_hi = fmaxf(m_hi, mx_hi);
        float cr_lo = exp2f(m_lo - mn_lo);
        float cr_hi = exp2f(m_hi - mn_hi);
        m_lo = mn_lo; m_hi = mn_hi;

        uint32_t p2[8][2];
        float sum_lo = 0.0f, sum_hi = 0.0f;
#pragma unroll
        for (int ntl = 0; ntl < 8; ntl++) {
            float p0 = exp2f(s[ntl][0] - m_lo);
            float p1 = exp2f(s[ntl][1] - m_lo);
            float pc = exp2f(s[ntl][2] - m_hi);
            float p3 = exp2f(s[ntl][3] - m_hi);
            sum_lo += p0 + p1;
            sum_hi += pc + p3;
            p2[ntl][0] = packh2(p0, p1);
            p2[ntl][1] = packh2(pc, p3);
        }
        // deferred l (per-thread partials, reduced once at the end)
        bool need = (cr_lo != 1.0f) || (cr_hi != 1.0f);
        if (__any_sync(0xffffffffu, need)) {
            l_lo = l_lo * cr_lo + sum_lo;
            l_hi = l_hi * cr_hi + sum_hi;
#pragma unroll
            for (int ntl = 0; ntl < 16; ntl++) {
                o[ntl][0] *= cr_lo; o[ntl][1] *= cr_lo;
                o[ntl][2] *= cr_hi; o[ntl][3] *= cr_hi;
            }
        } else {
            l_lo += sum_lo;
            l_hi += sum_hi;
        }

        // ---- PV(it) ----
        {
            const uint32_t vb = sbase + QTILE + (it & 1) * KVSTG + KVT;
#pragma unroll
            for (int kk = 0; kk < 4; kk++) {
                uint32_t pa[4] = {p2[2 * kk][0], p2[2 * kk][1],
                                  p2[2 * kk + 1][0], p2[2 * kk + 1][1]};
#pragma unroll
                for (int nd = 0; nd < 8; nd++) {
                    uint32_t vf[4];
                    ldsm4t(vf, vb + v_off + kk * 16 * KVS + nd * 32);
                    mma16816(o[2 * nd],     pa, &vf[0]);
                    mma16816(o[2 * nd + 1], pa, &vf[2]);
                }
            }
        }

        __syncthreads();                       // stage it&1 consumed
        if (it + 2 < nt) load_kv(it & 1, (it + 2) * 64);
        if (it + 2 < nt)
            asm volatile("cp.async.wait_group 1;" ::: "memory");
        else if (it + 1 < nt)
            asm volatile("cp.async.wait_group 0;" ::: "memory");
        __syncthreads();                       // loaded data visible

        // ---- S(it+1) — issued a full phase before its softmax ----
        if (it + 1 < nt) compute_S((it + 1) & 1);
    }

    // ---- epilogue: reduce deferred l, write fp16 attn ----
    l_lo += __shfl_xor_sync(0xffffffffu, l_lo, 1);
    l_lo += __shfl_xor_sync(0xffffffffu, l_lo, 2);
    l_hi += __shfl_xor_sync(0xffffffffu, l_hi, 1);
    l_hi += __shfl_xor_sync(0xffffffffu, l_hi, 2);
    const float inv_lo = 1.0f / l_lo;
    const float inv_hi = 1.0f / l_hi;
#pragma unroll
    for (int ntl = 0; ntl < 16; ntl++) {
        int col = h * D + ntl * 8 + (lane & 3) * 2;
        *(uint32_t*)&g_atf[(size_t)r_lo * QD + col] =
            packh2(o[ntl][0] * inv_lo, o[ntl][1] * inv_lo);
        *(uint32_t*)&g_atf[(size_t)r_hi * QD + col] =
            packh2(o[ntl][2] * inv_hi, o[ntl][3] * inv_hi);
    }
}

// ---------------------------------------------------------------------------
// Launch
// ---------------------------------------------------------------------------
extern "C" void kernel_launch(void* const* d_in, const int* in_sizes, int n_in,
                              void* d_out, int out_size) {
    const int*   positions = (const int*)d_in[0];
    const float* hs        = (const float*)d_in[1];
    const float* w_qkv     = (const float*)d_in[2];
    const float* w_o       = (const float*)d_in[3];
    const float* qnw       = (const float*)d_in[4];
    const float* knw       = (const float*)d_in[5];
    float*       out       = (float*)d_out;

    float* qkv_p;
    cudaGetSymbolAddress((void**)&qkv_p, g_qkv);

    __half *hsf, *wqf, *wof, *atf;
    cudaGetSymbolAddress((void**)&hsf, g_hsf);
    cudaGetSymbolAddress((void**)&wqf, g_wqf);
    cudaGetSymbolAddress((void**)&wof, g_wof);
    cudaGetSymbolAddress((void**)&atf, g_atf);

    static bool attr_set = false;
    if (!attr_set) {
        cudaFuncSetAttribute(gemm_hmma,
                             cudaFuncAttributeMaxDynamicSharedMemorySize, GSMEM);
        cudaFuncSetAttribute(flash_mma,
                             cudaFuncAttributeMaxDynamicSharedMemorySize, FSMEM);
        attr_set = true;
    }

    // 1) fused fp32->fp16 conversions
    cvt_f16<<<(N_HS + N_WQ + N_WO) / 1024, 256>>>(hs, w_qkv, w_o);
    // 2) QKV projection
    {
        dim3 grid(QKV_N / 128, T / 128);
        gemm_hmma<<<grid, 256, GSMEM>>>(hsf, wqf, qkv_p, QKV_N);
    }
    // 3) RoPE + RMSNorm
    rope_norm_kernel<<<T, 256>>>(positions, qnw, knw);
    // 4) Causal GQA attention (software-pipelined)
    {
        dim3 grid(T / 64, H);
        flash_mma<<<grid, 128, FSMEM>>>();
    }
    // 5) Output projection
    {
        dim3 grid(HID / 128, T / 128);
        gemm_hmma<<<grid, 256, GSMEM>>>(atf, wof, out, HID);
    }
}

// round 10
// speedup vs baseline: 1.1610x; 1.0450x over previous
#include <cuda_runtime.h>
#include <cuda_fp16.h>
#include <math.h>
#include <stdint.h>

#define T     4096
#define H     16
#define HKV   4
#define D     128
#define HID   2048
#define QKV_N ((H + 2 * HKV) * D)   // 3072
#define QD    (H * D)               // 2048
#define KD    (HKV * D)             // 512
#define EPSV  1e-5f
#define GK    2048
#define NCHUNK (GK / 32)

// fp32 scratch
__device__ float g_qkv[T * QKV_N];

// fp16 scratch
__device__ __half g_hsf[T * HID];
__device__ __half g_wqf[QKV_N * HID];
__device__ __half g_wof[HID * QD];
__device__ __half g_qf[T * QD];
__device__ __half g_kf[T * KD];
__device__ __half g_vf[T * KD];
__device__ __half g_atf[T * QD];

// ---------------------------------------------------------------------------
// helpers (sm_80-level PTX only)
// ---------------------------------------------------------------------------
__device__ __forceinline__ uint32_t smem_u32(const void* p) {
    uint32_t a;
    asm("{ .reg .u64 t; cvta.to.shared.u64 t, %1; cvt.u32.u64 %0, t; }"
        : "=r"(a) : "l"(p));
    return a;
}
__device__ __forceinline__ void cp16(uint32_t dst, const void* src) {
    asm volatile("cp.async.cg.shared.global [%0], [%1], 16;"
                 :: "r"(dst), "l"(src));
}
__device__ __forceinline__ void ldsm4(uint32_t* r, uint32_t addr) {
    asm volatile("ldmatrix.sync.aligned.m8n8.x4.shared.b16 {%0,%1,%2,%3}, [%4];"
                 : "=r"(r[0]), "=r"(r[1]), "=r"(r[2]), "=r"(r[3]) : "r"(addr));
}
__device__ __forceinline__ void ldsm4t(uint32_t* r, uint32_t addr) {
    asm volatile("ldmatrix.sync.aligned.m8n8.x4.trans.shared.b16 {%0,%1,%2,%3}, [%4];"
                 : "=r"(r[0]), "=r"(r[1]), "=r"(r[2]), "=r"(r[3]) : "r"(addr));
}
__device__ __forceinline__ void ldsm2(uint32_t* r, uint32_t addr) {
    asm volatile("ldmatrix.sync.aligned.m8n8.x2.shared.b16 {%0,%1}, [%2];"
                 : "=r"(r[0]), "=r"(r[1]) : "r"(addr));
}
__device__ __forceinline__ void mma16816(float* c, const uint32_t* a,
                                         const uint32_t* b) {
    asm volatile(
        "mma.sync.aligned.m16n8k16.row.col.f32.f16.f16.f32 "
        "{%0,%1,%2,%3}, {%4,%5,%6,%7}, {%8,%9}, {%0,%1,%2,%3};"
        : "+f"(c[0]), "+f"(c[1]), "+f"(c[2]), "+f"(c[3])
        : "r"(a[0]), "r"(a[1]), "r"(a[2]), "r"(a[3]), "r"(b[0]), "r"(b[1]));
}
__device__ __forceinline__ uint32_t packh2(float a, float b) {
    __half2 h = __floats2half2_rn(a, b);
    return *(uint32_t*)&h;
}
// 256B rows, 16B-granular XOR swizzle: conflict-free ldsm/ldsm4t + dense cp16
__device__ __forceinline__ uint32_t swz(uint32_t base, int row, int col16) {
    return base + row * 256 + ((col16 ^ (row & 7)) << 4);
}

// ---------------------------------------------------------------------------
// fused fp32 -> fp16 conversion (vectorized, 1 launch)
// ---------------------------------------------------------------------------
#define N_HS  (T * HID)
#define N_WQ  (QKV_N * HID)
#define N_WO  (HID * QD)

__global__ __launch_bounds__(256) void cvt_f16(const float* __restrict__ hs,
                                               const float* __restrict__ wq,
                                               const float* __restrict__ wo) {
    long idx = ((long)blockIdx.x * 256 + threadIdx.x) * 4;
    const float* src;
    __half* dst;
    long off;
    if (idx < N_HS)             { src = hs; dst = g_hsf; off = idx; }
    else if (idx < N_HS + N_WQ) { src = wq; dst = g_wqf; off = idx - N_HS; }
    else                        { src = wo; dst = g_wof; off = idx - N_HS - N_WQ; }
    float4 v = *(const float4*)(src + off);
    uint2 w = make_uint2(packh2(v.x, v.y), packh2(v.z, v.w));
    *(uint2*)(dst + off) = w;
}

// ---------------------------------------------------------------------------
// mma.sync fp16 NT GEMM; 2 CTAs/SM via launch bounds.
// ---------------------------------------------------------------------------
#define TILE_B   (128 * 80)
#define STAGE_B  (2 * TILE_B)
#define GSMEM    (3 * STAGE_B)

__global__ __launch_bounds__(256, 2)
void gemm_hmma(const __half* __restrict__ A,
               const __half* __restrict__ B,
               float* __restrict__ C, int N) {
    extern __shared__ char smem[];
    const uint32_t sbase = smem_u32(smem);
    const int tid  = threadIdx.x;
    const int wid  = tid >> 5;
    const int lane = tid & 31;
    const int wm   = wid & 1;
    const int wn   = wid >> 1;
    const int bm   = blockIdx.y * 128;
    const int bn   = blockIdx.x * 128;

    const __half* srcs[2] = {A + (size_t)bm * GK, B + (size_t)bn * GK};

    auto load_chunk = [&](int stage, int k0) {
        uint32_t db = sbase + stage * STAGE_B;
#pragma unroll
        for (int t = 0; t < 2; t++) {
            const __half* s = srcs[t] + k0;
#pragma unroll
            for (int i = 0; i < 2; i++) {
                int seg = i * 256 + tid;
                int row = seg >> 2, c16 = seg & 3;
                cp16(db + t * TILE_B + row * 80 + c16 * 16,
                     s + (size_t)row * GK + c16 * 8);
            }
        }
        asm volatile("cp.async.commit_group;" ::: "memory");
    };

    float acc[4][4][4];
#pragma unroll
    for (int mt = 0; mt < 4; mt++)
#pragma unroll
        for (int nt = 0; nt < 4; nt++)
#pragma unroll
            for (int r = 0; r < 4; r++) acc[mt][nt][r] = 0.0f;

    load_chunk(0, 0);
    load_chunk(1, 32);

    const int arow  = lane & 15;
    const int akoff = (lane >> 4) * 16;
    const int brow  = lane & 7;
    const int bkoff = ((lane >> 3) & 1) * 16;

    for (int i = 0; i < NCHUNK; i++) {
        if (i + 2 < NCHUNK)
            asm volatile("cp.async.wait_group 1;" ::: "memory");
        else
            asm volatile("cp.async.wait_group 0;" ::: "memory");
        __syncthreads();

        uint32_t s0 = sbase + (i % 3) * STAGE_B;
        uint32_t aB = s0, bB = s0 + TILE_B;

#pragma unroll
        for (int kk = 0; kk < 2; kk++) {
            const int kb = kk * 32;
            uint32_t af[4][4], bf[4][2];
#pragma unroll
            for (int mt = 0; mt < 4; mt++)
                ldsm4(af[mt], aB + (uint32_t)((wm * 64 + mt * 16 + arow) * 80 + kb + akoff));
#pragma unroll
            for (int nt = 0; nt < 4; nt++)
                ldsm2(bf[nt], bB + (uint32_t)((wn * 32 + nt * 8 + brow) * 80 + kb + bkoff));
#pragma unroll
            for (int mt = 0; mt < 4; mt++)
#pragma unroll
                for (int nt = 0; nt < 4; nt++)
                    mma16816(acc[mt][nt], af[mt], bf[nt]);
        }
        __syncthreads();
        if (i + 2 < NCHUNK) load_chunk((i + 2) % 3, (i + 2) * 32);
    }

#pragma unroll
    for (int mt = 0; mt < 4; mt++) {
        const int row0 = bm + wm * 64 + mt * 16 + (lane >> 2);
#pragma unroll
        for (int nt = 0; nt < 4; nt++) {
            const int col = bn + wn * 32 + nt * 8 + (lane & 3) * 2;
            *(float2*)&C[(size_t)row0 * N + col] =
                make_float2(acc[mt][nt][0], acc[mt][nt][1]);
            *(float2*)&C[(size_t)(row0 + 8) * N + col] =
                make_float2(acc[mt][nt][2], acc[mt][nt][3]);
        }
    }
}

// ---------------------------------------------------------------------------
// RoPE + RMSNorm (unchanged from round 9)
// ---------------------------------------------------------------------------
__global__ __launch_bounds__(256) void rope_norm_kernel(
    const int* __restrict__ positions,
    const float* __restrict__ qnw,
    const float* __restrict__ knw) {
    const int t    = blockIdx.x;
    const int tid  = threadIdx.x;
    const int lane = tid & 31;
    const float pos  = (float)positions[t];
    const float qpre = 0.08838834764831845f * 1.4426950408889634f;

    __shared__ float cs[64], sn[64];
    __shared__ float red[8];

    if (tid < 64) {
        float inv = powf(10000.0f, -(float)(2 * tid) * (1.0f / 128.0f));
        sincosf(pos * inv, &sn[tid], &cs[tid]);
    }
    __syncthreads();

    const float* base = g_qkv + (size_t)t * QKV_N;

    const int head = tid >> 4;
    const int c4   = (tid & 15) * 4;
    float4 a = *(const float4*)(base + head * 128 + c4);
    float4 b = *(const float4*)(base + head * 128 + 64 + c4);
    float o1[4], o2[4];
    {
        const float av[4] = {a.x, a.y, a.z, a.w};
        const float bv[4] = {b.x, b.y, b.z, b.w};
        float ss = 0.0f;
#pragma unroll
        for (int j = 0; j < 4; j++) {
            float cv = cs[c4 + j], sv = sn[c4 + j];
            o1[j] = av[j] * cv - bv[j] * sv;
            o2[j] = bv[j] * cv + av[j] * sv;
            ss += o1[j] * o1[j] + o2[j] * o2[j];
        }
#pragma unroll
        for (int off = 16; off; off >>= 1)
            ss += __shfl_xor_sync(0xffffffffu, ss, off);
        if (lane == 0) red[tid >> 5] = ss;
    }
    __syncthreads();
    {
        float tot = red[0] + red[1] + red[2] + red[3] +
                    red[4] + red[5] + red[6] + red[7];
        float qs = rsqrtf(tot * (1.0f / QD) + EPSV) * qpre;
        float4 w1 = *(const float4*)(qnw + head * 128 + c4);
        float4 w2 = *(const float4*)(qnw + head * 128 + 64 + c4);
        __half* dst = g_qf + (size_t)t * QD + head * 128 + c4;
        *(uint2*)dst = make_uint2(packh2(o1[0] * qs * w1.x, o1[1] * qs * w1.y),
                                  packh2(o1[2] * qs * w1.z, o1[3] * qs * w1.w));
        *(uint2*)(dst + 64) = make_uint2(packh2(o2[0] * qs * w2.x, o2[1] * qs * w2.y),
                                         packh2(o2[2] * qs * w2.z, o2[3] * qs * w2.w));
    }
    __syncthreads();

    const int khead = tid >> 6;
    const int fi    = tid & 63;
    const float* kp = base + QD + khead * 128 + fi;
    float k1, k2;
    {
        float ka = kp[0], kb = kp[64];
        float cv = cs[fi], sv = sn[fi];
        k1 = ka * cv - kb * sv;
        k2 = kb * cv + ka * sv;
        float ss = k1 * k1 + k2 * k2;
#pragma unroll
        for (int off = 16; off; off >>= 1)
            ss += __shfl_xor_sync(0xffffffffu, ss, off);
        if (lane == 0) red[tid >> 5] = ss;
    }
    __syncthreads();
    {
        float tot = red[0] + red[1] + red[2] + red[3] +
                    red[4] + red[5] + red[6] + red[7];
        float ks = rsqrtf(tot * (1.0f / KD) + EPSV);
        __half* dst = g_kf + (size_t)t * KD + khead * 128 + fi;
        dst[0]  = __float2half_rn(k1 * ks * knw[khead * 128 + fi]);
        dst[64] = __float2half_rn(k2 * ks * knw[khead * 128 + 64 + fi]);
    }

    {
        float2 v2 = *(const float2*)(base + QD + KD + tid * 2);
        *(uint32_t*)(g_vf + (size_t)t * KD + tid * 2) = packh2(v2.x, v2.y);
    }
}

// ---------------------------------------------------------------------------
// flash_mma: causal GQA attention, fp16 mma, software-pipelined, 3 CTAs/SM.
// CTA: 64 queries x 1 head, 4 warps. 64-key tiles. Swizzled 256B smem rows.
// K double-buffered, V single-buffered (refill committed post-PV barrier,
// consumed after a full S+softmax window). Per iter: softmax(it) -> PV(it)
// -> commit{V(it+1),K(it+2)} -> S(it+1).
// ---------------------------------------------------------------------------
#define QSZ     16384                      // 64 rows x 256 B
#define KSZ     16384
#define VSZ     16384
#define FSMEM   (QSZ + 2 * KSZ + VSZ)      // 65536 -> 3 CTAs/SM

__global__ __launch_bounds__(128, 3) void flash_mma() {
    extern __shared__ char smem[];
    const uint32_t sbase = smem_u32(smem);
    const int tid  = threadIdx.x;
    const int wg   = tid >> 5;
    const int lane = tid & 31;
    const int h    = blockIdx.y;
    const int kvh  = h >> 2;
    const int qb   = (int)gridDim.x - 1 - (int)blockIdx.x;
    const int q0   = qb * 64;
    const int nt   = qb + 1;

    const uint32_t qB = sbase;
    const uint32_t vB = sbase + QSZ + 2 * KSZ;

    // ---- prologue loads: C0 = {Q, K0, V0}, C1 = {K1} ----
    {
        const __half* qs = g_qf + (size_t)q0 * QD + h * D;
        const __half* ks = g_kf + (size_t)0 * KD + kvh * D;
        const __half* vs = g_vf + (size_t)0 * KD + kvh * D;
#pragma unroll
        for (int i = 0; i < 8; i++) {
            int seg = i * 128 + tid;
            int row = seg >> 4, c = seg & 15;
            cp16(swz(qB, row, c),       qs + (size_t)row * QD + c * 8);
            cp16(swz(sbase + QSZ, row, c), ks + (size_t)row * KD + c * 8);
            cp16(swz(vB, row, c),       vs + (size_t)row * KD + c * 8);
        }
        asm volatile("cp.async.commit_group;" ::: "memory");
    }
    auto load_k = [&](int stage, int k0) {
        const __half* ks = g_kf + (size_t)k0 * KD + kvh * D;
        uint32_t kb = sbase + QSZ + stage * KSZ;
#pragma unroll
        for (int i = 0; i < 8; i++) {
            int seg = i * 128 + tid;
            int row = seg >> 4, c = seg & 15;
            cp16(swz(kb, row, c), ks + (size_t)row * KD + c * 8);
        }
    };
    auto load_v = [&](int k0) {
        const __half* vs = g_vf + (size_t)k0 * KD + kvh * D;
#pragma unroll
        for (int i = 0; i < 8; i++) {
            int seg = i * 128 + tid;
            int row = seg >> 4, c = seg & 15;
            cp16(swz(vB, row, c), vs + (size_t)row * KD + c * 8);
        }
    };
    if (nt > 1) {
        load_k(1, 64);
        asm volatile("cp.async.commit_group;" ::: "memory");
        asm volatile("cp.async.wait_group 1;" ::: "memory");
    } else {
        asm volatile("cp.async.wait_group 0;" ::: "memory");
    }
    __syncthreads();

    // per-lane fragment coordinates
    const int qrow = wg * 16 + (lane & 15);
    const int qhi  = lane >> 4;
    const int krow = ((lane >> 4) << 3) + (lane & 7);
    const int khi  = (lane >> 3) & 1;
    const int vrow = (((lane >> 3) & 1) << 3) + (lane & 7);
    const int vhi  = lane >> 4;
    const int r_lo = q0 + wg * 16 + (lane >> 2);
    const int r_hi = r_lo + 8;

    float o[16][4];
#pragma unroll
    for (int ntl = 0; ntl < 16; ntl++)
#pragma unroll
        for (int r = 0; r < 4; r++) o[ntl][r] = 0.0f;
    float m_lo = -1e30f, m_hi = -1e30f, l_lo = 0.0f, l_hi = 0.0f;

    float s[8][4];

    auto compute_S = [&](int stage) {
        const uint32_t kb = sbase + QSZ + stage * KSZ;
#pragma unroll
        for (int ntl = 0; ntl < 8; ntl++)
#pragma unroll
            for (int r = 0; r < 4; r++) s[ntl][r] = 0.0f;
#pragma unroll
        for (int kk = 0; kk < 8; kk++) {
            uint32_t af[4];
            ldsm4(af, swz(qB, qrow, kk * 2 + qhi));
#pragma unroll
            for (int np = 0; np < 4; np++) {
                uint32_t bf[4];
                ldsm4(bf, swz(kb, np * 16 + krow, kk * 2 + khi));
                mma16816(s[2 * np],     af, &bf[0]);
                mma16816(s[2 * np + 1], af, &bf[2]);
            }
        }
    };

    compute_S(0);

    for (int it = 0; it < nt; it++) {
        // ---- softmax(it) ----
        if (it == nt - 1) {
#pragma unroll
            for (int ntl = 0; ntl < 8; ntl++) {
#pragma unroll
                for (int c = 0; c < 2; c++) {
                    int key = it * 64 + ntl * 8 + (lane & 3) * 2 + c;
                    if (key > r_lo) s[ntl][c]     = -1e30f;
                    if (key > r_hi) s[ntl][2 + c] = -1e30f;
                }
            }
        }
        float mx_lo = -1e30f, mx_hi = -1e30f;
#pragma unroll
        for (int ntl = 0; ntl < 8; ntl++) {
            mx_lo = fmaxf(mx_lo, fmaxf(s[ntl][0], s[ntl][1]));
            mx_hi = fmaxf(mx_hi, fmaxf(s[ntl][2], s[ntl][3]));
        }
        mx_lo = fmaxf(mx_lo, __shfl_xor_sync(0xffffffffu, mx_lo, 1));
        mx_lo = fmaxf(mx_lo, __shfl_xor_sync(0xffffffffu, mx_lo, 2));
        mx_hi = fmaxf(mx_hi, __shfl_xor_sync(0xffffffffu, mx_hi, 1));
        mx_hi = fmaxf(mx_hi, __shfl_xor_sync(0xffffffffu, mx_hi, 2));
        float mn_lo = fmaxf(m_lo, mx_lo);
        float mn_hi = fmaxf(m_hi, mx_hi);
        float cr_lo = exp2f(m_lo - mn_lo);
        float cr_hi = exp2f(m_hi - mn_hi);
        m_lo = mn_lo; m_hi = mn_hi;

        uint32_t p2[8][2];
        float sum_lo = 0.0f, sum_hi = 0.0f;
#pragma unroll
        for (int ntl = 0; ntl < 8; ntl++) {
            float p0 = exp2f(s[ntl][0] - m_lo);
            float p1 = exp2f(s[ntl][1] - m_lo);
            float pc = exp2f(s[ntl][2] - m_hi);
            float p3 = exp2f(s[ntl][3] - m_hi);
            sum_lo += p0 + p1;
            sum_hi += pc + p3;
            p2[ntl][0] = packh2(p0, p1);
            p2[ntl][1] = packh2(pc, p3);
        }
        bool need = (cr_lo != 1.0f) || (cr_hi != 1.0f);
        if (__any_sync(0xffffffffu, need)) {
            l_lo = l_lo * cr_lo + sum_lo;
            l_hi = l_hi * cr_hi + sum_hi;
#pragma unroll
            for (int ntl = 0; ntl < 16; ntl++) {
                o[ntl][0] *= cr_lo; o[ntl][1] *= cr_lo;
                o[ntl][2] *= cr_hi; o[ntl][3] *= cr_hi;
            }
        } else {
            l_lo += sum_lo;
            l_hi += sum_hi;
        }

        // ---- V(it) guaranteed resident: all committed groups drained ----
        asm volatile("cp.async.wait_group 0;" ::: "memory");
        __syncthreads();

        // ---- PV(it) ----
#pragma unroll
        for (int kk = 0; kk < 4; kk++) {
            uint32_t pa[4] = {p2[2 * kk][0], p2[2 * kk][1],
                              p2[2 * kk + 1][0], p2[2 * kk + 1][1]};
#pragma unroll
            for (int nd = 0; nd < 8; nd++) {
                uint32_t vf[4];
                ldsm4t(vf, swz(vB, kk * 16 + vrow, nd * 2 + vhi));
                mma16816(o[2 * nd],     pa, &vf[0]);
                mma16816(o[2 * nd + 1], pa, &vf[2]);
            }
        }
        __syncthreads();                      // V buffer + K(it) buffer free

        // ---- prefetch G(it) = {V(it+1), K(it+2)} ----
        if (it + 1 < nt) {
            load_v((it + 1) * 64);
            if (it + 2 < nt) load_k(it & 1, (it + 2) * 64);
            asm volatile("cp.async.commit_group;" ::: "memory");
            // ---- S(it+1): K(it+1) already resident (drained above) ----
            compute_S((it + 1) & 1);
        }
    }

    // ---- epilogue ----
    l_lo += __shfl_xor_sync(0xffffffffu, l_lo, 1);
    l_lo += __shfl_xor_sync(0xffffffffu, l_lo, 2);
    l_hi += __shfl_xor_sync(0xffffffffu, l_hi, 1);
    l_hi += __shfl_xor_sync(0xffffffffu, l_hi, 2);
    const float inv_lo = 1.0f / l_lo;
    const float inv_hi = 1.0f / l_hi;
#pragma unroll
    for (int ntl = 0; ntl < 16; ntl++) {
        int col = h * D + ntl * 8 + (lane & 3) * 2;
        *(uint32_t*)&g_atf[(size_t)r_lo * QD + col] =
            packh2(o[ntl][0] * inv_lo, o[ntl][1] * inv_lo);
        *(uint32_t*)&g_atf[(size_t)r_hi * QD + col] =
            packh2(o[ntl][2] * inv_hi, o[ntl][3] * inv_hi);
    }
}

// ---------------------------------------------------------------------------
// Launch
// ---------------------------------------------------------------------------
extern "C" void kernel_launch(void* const* d_in, const int* in_sizes, int n_in,
                              void* d_out, int out_size) {
    const int*   positions = (const int*)d_in[0];
    const float* hs        = (const float*)d_in[1];
    const float* w_qkv     = (const float*)d_in[2];
    const float* w_o       = (const float*)d_in[3];
    const float* qnw       = (const float*)d_in[4];
    const float* knw       = (const float*)d_in[5];
    float*       out       = (float*)d_out;

    float* qkv_p;
    cudaGetSymbolAddress((void**)&qkv_p, g_qkv);

    __half *hsf, *wqf, *wof, *atf;
    cudaGetSymbolAddress((void**)&hsf, g_hsf);
    cudaGetSymbolAddress((void**)&wqf, g_wqf);
    cudaGetSymbolAddress((void**)&wof, g_wof);
    cudaGetSymbolAddress((void**)&atf, g_atf);

    static bool attr_set = false;
    if (!attr_set) {
        cudaFuncSetAttribute(gemm_hmma,
                             cudaFuncAttributeMaxDynamicSharedMemorySize, GSMEM);
        cudaFuncSetAttribute(flash_mma,
                             cudaFuncAttributeMaxDynamicSharedMemorySize, FSMEM);
        attr_set = true;
    }

    // 1) fused fp32->fp16 conversions
    cvt_f16<<<(N_HS + N_WQ + N_WO) / 1024, 256>>>(hs, w_qkv, w_o);
    // 2) QKV projection
    {
        dim3 grid(QKV_N / 128, T / 128);
        gemm_hmma<<<grid, 256, GSMEM>>>(hsf, wqf, qkv_p, QKV_N);
    }
    // 3) RoPE + RMSNorm
    rope_norm_kernel<<<T, 256>>>(positions, qnw, knw);
    // 4) Causal GQA attention (3 CTAs/SM)
    {
        dim3 grid(T / 64, H);
        flash_mma<<<grid, 128, FSMEM>>>();
    }
    // 5) Output projection
    {
        dim3 grid(HID / 128, T / 128);
        gemm_hmma<<<grid, 256, GSMEM>>>(atf, wof, out, HID);
    }
}

// round 11
// speedup vs baseline: 1.1633x; 1.0020x over previous
#include <cuda_runtime.h>
#include <cuda_fp16.h>
#include <math.h>
#include <stdint.h>

#define T     4096
#define H     16
#define HKV   4
#define D     128
#define HID   2048
#define QKV_N ((H + 2 * HKV) * D)   // 3072
#define QD    (H * D)               // 2048
#define KD    (HKV * D)             // 512
#define EPSV  1e-5f
#define GK    2048
#define NCHUNK (GK / 32)

// fp16 scratch
__device__ __half g_qkvh[T * QKV_N];   // QKV projection output (fp16)
__device__ __half g_hsf[T * HID];
__device__ __half g_wqf[QKV_N * HID];
__device__ __half g_wof[HID * QD];
__device__ __half g_qf[T * QD];
__device__ __half g_kf[T * KD];
__device__ __half g_atf[T * QD];

// ---------------------------------------------------------------------------
// helpers (sm_80-level PTX only)
// ---------------------------------------------------------------------------
__device__ __forceinline__ uint32_t smem_u32(const void* p) {
    uint32_t a;
    asm("{ .reg .u64 t; cvta.to.shared.u64 t, %1; cvt.u32.u64 %0, t; }"
        : "=r"(a) : "l"(p));
    return a;
}
__device__ __forceinline__ void cp16(uint32_t dst, const void* src) {
    asm volatile("cp.async.cg.shared.global [%0], [%1], 16;"
                 :: "r"(dst), "l"(src));
}
__device__ __forceinline__ void ldsm4(uint32_t* r, uint32_t addr) {
    asm volatile("ldmatrix.sync.aligned.m8n8.x4.shared.b16 {%0,%1,%2,%3}, [%4];"
                 : "=r"(r[0]), "=r"(r[1]), "=r"(r[2]), "=r"(r[3]) : "r"(addr));
}
__device__ __forceinline__ void ldsm4t(uint32_t* r, uint32_t addr) {
    asm volatile("ldmatrix.sync.aligned.m8n8.x4.trans.shared.b16 {%0,%1,%2,%3}, [%4];"
                 : "=r"(r[0]), "=r"(r[1]), "=r"(r[2]), "=r"(r[3]) : "r"(addr));
}
__device__ __forceinline__ void ldsm2(uint32_t* r, uint32_t addr) {
    asm volatile("ldmatrix.sync.aligned.m8n8.x2.shared.b16 {%0,%1}, [%2];"
                 : "=r"(r[0]), "=r"(r[1]) : "r"(addr));
}
__device__ __forceinline__ void mma16816(float* c, const uint32_t* a,
                                         const uint32_t* b) {
    asm volatile(
        "mma.sync.aligned.m16n8k16.row.col.f32.f16.f16.f32 "
        "{%0,%1,%2,%3}, {%4,%5,%6,%7}, {%8,%9}, {%0,%1,%2,%3};"
        : "+f"(c[0]), "+f"(c[1]), "+f"(c[2]), "+f"(c[3])
        : "r"(a[0]), "r"(a[1]), "r"(a[2]), "r"(a[3]), "r"(b[0]), "r"(b[1]));
}
__device__ __forceinline__ uint32_t packh2(float a, float b) {
    __half2 h = __floats2half2_rn(a, b);
    return *(uint32_t*)&h;
}
// 256B rows, 16B-granular XOR swizzle
__device__ __forceinline__ uint32_t swz(uint32_t base, int row, int col16) {
    return base + row * 256 + ((col16 ^ (row & 7)) << 4);
}

// ---------------------------------------------------------------------------
// fused fp32 -> fp16 conversion (vectorized, 1 launch)
// ---------------------------------------------------------------------------
#define N_HS  (T * HID)
#define N_WQ  (QKV_N * HID)
#define N_WO  (HID * QD)

__global__ __launch_bounds__(256) void cvt_f16(const float* __restrict__ hs,
                                               const float* __restrict__ wq,
                                               const float* __restrict__ wo) {
    long idx = ((long)blockIdx.x * 256 + threadIdx.x) * 4;
    const float* src;
    __half* dst;
    long off;
    if (idx < N_HS)             { src = hs; dst = g_hsf; off = idx; }
    else if (idx < N_HS + N_WQ) { src = wq; dst = g_wqf; off = idx - N_HS; }
    else                        { src = wo; dst = g_wof; off = idx - N_HS - N_WQ; }
    float4 v = *(const float4*)(src + off);
    uint2 w = make_uint2(packh2(v.x, v.y), packh2(v.z, v.w));
    *(uint2*)(dst + off) = w;
}

// ---------------------------------------------------------------------------
// mma.sync fp16 NT GEMM; single barrier per chunk; fp16 or fp32 output.
// ---------------------------------------------------------------------------
#define TILE_B   (128 * 80)
#define STAGE_B  (2 * TILE_B)
#define GSMEM    (3 * STAGE_B)

template<bool HALF_OUT>
__global__ __launch_bounds__(256, 2)
void gemm_hmma(const __half* __restrict__ A,
               const __half* __restrict__ B,
               void* __restrict__ Cv, int N) {
    extern __shared__ char smem[];
    const uint32_t sbase = smem_u32(smem);
    const int tid  = threadIdx.x;
    const int wid  = tid >> 5;
    const int lane = tid & 31;
    const int wm   = wid & 1;
    const int wn   = wid >> 1;
    const int bm   = blockIdx.y * 128;
    const int bn   = blockIdx.x * 128;

    const __half* srcs[2] = {A + (size_t)bm * GK, B + (size_t)bn * GK};

    auto load_chunk = [&](int stage, int k0) {
        uint32_t db = sbase + stage * STAGE_B;
#pragma unroll
        for (int t = 0; t < 2; t++) {
            const __half* s = srcs[t] + k0;
#pragma unroll
            for (int i = 0; i < 2; i++) {
                int seg = i * 256 + tid;
                int row = seg >> 2, c16 = seg & 3;
                cp16(db + t * TILE_B + row * 80 + c16 * 16,
                     s + (size_t)row * GK + c16 * 8);
            }
        }
        asm volatile("cp.async.commit_group;" ::: "memory");
    };

    float acc[4][4][4];
#pragma unroll
    for (int mt = 0; mt < 4; mt++)
#pragma unroll
        for (int nt = 0; nt < 4; nt++)
#pragma unroll
            for (int r = 0; r < 4; r++) acc[mt][nt][r] = 0.0f;

    load_chunk(0, 0);
    load_chunk(1, 32);

    const int arow  = lane & 15;
    const int akoff = (lane >> 4) * 16;
    const int brow  = lane & 7;
    const int bkoff = ((lane >> 3) & 1) * 16;

    for (int i = 0; i < NCHUNK; i++) {
        if (i + 1 < NCHUNK)
            asm volatile("cp.async.wait_group 1;" ::: "memory");
        else
            asm volatile("cp.async.wait_group 0;" ::: "memory");
        __syncthreads();   // single barrier per chunk: top-bar proves all warps
                           // finished reading stage (i+2)%3 (== stage of iter i-1)
        if (i + 2 < NCHUNK) load_chunk((i + 2) % 3, (i + 2) * 32);

        uint32_t s0 = sbase + (i % 3) * STAGE_B;
        uint32_t aB = s0, bB = s0 + TILE_B;

#pragma unroll
        for (int kk = 0; kk < 2; kk++) {
            const int kb = kk * 32;
            uint32_t af[4][4], bf[4][2];
#pragma unroll
            for (int mt = 0; mt < 4; mt++)
                ldsm4(af[mt], aB + (uint32_t)((wm * 64 + mt * 16 + arow) * 80 + kb + akoff));
#pragma unroll
            for (int nt = 0; nt < 4; nt++)
                ldsm2(bf[nt], bB + (uint32_t)((wn * 32 + nt * 8 + brow) * 80 + kb + bkoff));
#pragma unroll
            for (int mt = 0; mt < 4; mt++)
#pragma unroll
                for (int nt = 0; nt < 4; nt++)
                    mma16816(acc[mt][nt], af[mt], bf[nt]);
        }
    }

#pragma unroll
    for (int mt = 0; mt < 4; mt++) {
        const int row0 = bm + wm * 64 + mt * 16 + (lane >> 2);
#pragma unroll
        for (int nt = 0; nt < 4; nt++) {
            const int col = bn + wn * 32 + nt * 8 + (lane & 3) * 2;
            if (HALF_OUT) {
                __half* C = (__half*)Cv;
                *(uint32_t*)&C[(size_t)row0 * N + col] =
                    packh2(acc[mt][nt][0], acc[mt][nt][1]);
                *(uint32_t*)&C[(size_t)(row0 + 8) * N + col] =
                    packh2(acc[mt][nt][2], acc[mt][nt][3]);
            } else {
                float* C = (float*)Cv;
                *(float2*)&C[(size_t)row0 * N + col] =
                    make_float2(acc[mt][nt][0], acc[mt][nt][1]);
                *(float2*)&C[(size_t)(row0 + 8) * N + col] =
                    make_float2(acc[mt][nt][2], acc[mt][nt][3]);
            }
        }
    }
}

// ---------------------------------------------------------------------------
// RoPE + RMSNorm, reads fp16 qkv. Emits fp16 q (pre-scaled), k.
// ---------------------------------------------------------------------------
__global__ __launch_bounds__(256) void rope_norm_kernel(
    const int* __restrict__ positions,
    const float* __restrict__ qnw,
    const float* __restrict__ knw) {
    const int t    = blockIdx.x;
    const int tid  = threadIdx.x;
    const int lane = tid & 31;
    const float pos  = (float)positions[t];
    const float qpre = 0.08838834764831845f * 1.4426950408889634f;

    __shared__ float cs[64], sn[64];
    __shared__ float red[8];

    if (tid < 64) {
        float inv = powf(10000.0f, -(float)(2 * tid) * (1.0f / 128.0f));
        sincosf(pos * inv, &sn[tid], &cs[tid]);
    }
    __syncthreads();

    const __half* base = g_qkvh + (size_t)t * QKV_N;

    // ---- Q: thread owns 4 rotation pairs ----
    const int head = tid >> 4;
    const int c4   = (tid & 15) * 4;
    float av[4], bv[4];
    {
        uint2 ar = *(const uint2*)(base + head * 128 + c4);
        uint2 br = *(const uint2*)(base + head * 128 + 64 + c4);
        __half2* ah = (__half2*)&ar;
        __half2* bh = (__half2*)&br;
        float2 a0 = __half22float2(ah[0]), a1 = __half22float2(ah[1]);
        float2 b0 = __half22float2(bh[0]), b1 = __half22float2(bh[1]);
        av[0] = a0.x; av[1] = a0.y; av[2] = a1.x; av[3] = a1.y;
        bv[0] = b0.x; bv[1] = b0.y; bv[2] = b1.x; bv[3] = b1.y;
    }
    float o1[4], o2[4];
    {
        float ss = 0.0f;
#pragma unroll
        for (int j = 0; j < 4; j++) {
            float cv = cs[c4 + j], sv = sn[c4 + j];
            o1[j] = av[j] * cv - bv[j] * sv;
            o2[j] = bv[j] * cv + av[j] * sv;
            ss += o1[j] * o1[j] + o2[j] * o2[j];
        }
#pragma unroll
        for (int off = 16; off; off >>= 1)
            ss += __shfl_xor_sync(0xffffffffu, ss, off);
        if (lane == 0) red[tid >> 5] = ss;
    }
    __syncthreads();
    {
        float tot = red[0] + red[1] + red[2] + red[3] +
                    red[4] + red[5] + red[6] + red[7];
        float qs = rsqrtf(tot * (1.0f / QD) + EPSV) * qpre;
        float4 w1 = *(const float4*)(qnw + head * 128 + c4);
        float4 w2 = *(const float4*)(qnw + head * 128 + 64 + c4);
        __half* dst = g_qf + (size_t)t * QD + head * 128 + c4;
        *(uint2*)dst = make_uint2(packh2(o1[0] * qs * w1.x, o1[1] * qs * w1.y),
                                  packh2(o1[2] * qs * w1.z, o1[3] * qs * w1.w));
        *(uint2*)(dst + 64) = make_uint2(packh2(o2[0] * qs * w2.x, o2[1] * qs * w2.y),
                                         packh2(o2[2] * qs * w2.z, o2[3] * qs * w2.w));
    }
    __syncthreads();

    // ---- K: thread owns 1 rotation pair ----
    const int khead = tid >> 6;
    const int fi    = tid & 63;
    const __half* kp = base + QD + khead * 128 + fi;
    float k1, k2;
    {
        float ka = __half2float(kp[0]), kb = __half2float(kp[64]);
        float cv = cs[fi], sv = sn[fi];
        k1 = ka * cv - kb * sv;
        k2 = kb * cv + ka * sv;
        float ss = k1 * k1 + k2 * k2;
#pragma unroll
        for (int off = 16; off; off >>= 1)
            ss += __shfl_xor_sync(0xffffffffu, ss, off);
        if (lane == 0) red[tid >> 5] = ss;
    }
    __syncthreads();
    {
        float tot = red[0] + red[1] + red[2] + red[3] +
                    red[4] + red[5] + red[6] + red[7];
        float ks = rsqrtf(tot * (1.0f / KD) + EPSV);
        __half* dst = g_kf + (size_t)t * KD + khead * 128 + fi;
        dst[0]  = __float2half_rn(k1 * ks * knw[khead * 128 + fi]);
        dst[64] = __float2half_rn(k2 * ks * knw[khead * 128 + 64 + fi]);
    }
    // V: consumed directly from g_qkvh by flash (no copy)
}

// ---------------------------------------------------------------------------
// flash_mma: causal GQA attention, fp16 mma, software-pipelined.
// CTA: 64 queries x 1 head, 4 warps, 128-key tiles, 2 CTAs/SM.
// K double-buffered (2x32KB), V single-buffered (32KB). V read directly
// from g_qkvh. Per iter: softmax(it) -> PV(it) -> commit{V(it+1),K(it+2)}
// -> S(it+1).
// ---------------------------------------------------------------------------
#define QSZ     16384                      // 64 rows x 256 B
#define KSZ     32768                      // 128 rows x 256 B
#define VSZ     32768
#define FSMEM   (QSZ + 2 * KSZ + VSZ)      // 114688 -> 2 CTAs/SM

__global__ __launch_bounds__(128, 2) void flash_mma() {
    extern __shared__ char smem[];
    const uint32_t sbase = smem_u32(smem);
    const int tid  = threadIdx.x;
    const int wg   = tid >> 5;
    const int lane = tid & 31;
    const int h    = blockIdx.y;
    const int kvh  = h >> 2;
    const int qb   = (int)gridDim.x - 1 - (int)blockIdx.x;
    const int q0   = qb * 64;
    const int nt   = qb / 2 + 1;           // 128-key tiles covering [0, q0+64)

    const uint32_t qB = sbase;
    const uint32_t vB = sbase + QSZ + 2 * KSZ;

    auto load_k = [&](int stage, int k0) {
        const __half* ks = g_kf + (size_t)k0 * KD + kvh * D;
        uint32_t kb = sbase + QSZ + stage * KSZ;
#pragma unroll
        for (int i = 0; i < 16; i++) {
            int seg = i * 128 + tid;           // 0..2047
            int row = seg >> 4, c = seg & 15;
            cp16(swz(kb, row, c), ks + (size_t)row * KD + c * 8);
        }
    };
    auto load_v = [&](int k0) {
        const __half* vs = g_qkvh + (size_t)k0 * QKV_N + QD + KD + kvh * D;
#pragma unroll
        for (int i = 0; i < 16; i++) {
            int seg = i * 128 + tid;
            int row = seg >> 4, c = seg & 15;
            cp16(swz(vB, row, c), vs + (size_t)row * QKV_N + c * 8);
        }
    };

    // ---- prologue: {Q, K0, V0} then {K1} ----
    {
        const __half* qs = g_qf + (size_t)q0 * QD + h * D;
#pragma unroll
        for (int i = 0; i < 8; i++) {
            int seg = i * 128 + tid;           // 0..1023
            int row = seg >> 4, c = seg & 15;
            cp16(swz(qB, row, c), qs + (size_t)row * QD + c * 8);
        }
        load_k(0, 0);
        load_v(0);
        asm volatile("cp.async.commit_group;" ::: "memory");
    }
    if (nt > 1) {
        load_k(1, 128);
        asm volatile("cp.async.commit_group;" ::: "memory");
        asm volatile("cp.async.wait_group 1;" ::: "memory");
    } else {
        asm volatile("cp.async.wait_group 0;" ::: "memory");
    }
    __syncthreads();

    // per-lane fragment coordinates
    const int qrow = wg * 16 + (lane & 15);
    const int qhi  = lane >> 4;
    const int krow = ((lane >> 4) << 3) + (lane & 7);
    const int khi  = (lane >> 3) & 1;
    const int vrow = (((lane >> 3) & 1) << 3) + (lane & 7);
    const int vhi  = lane >> 4;
    const int r_lo = q0 + wg * 16 + (lane >> 2);
    const int r_hi = r_lo + 8;

    float o[16][4];
#pragma unroll
    for (int ntl = 0; ntl < 16; ntl++)
#pragma unroll
        for (int r = 0; r < 4; r++) o[ntl][r] = 0.0f;
    float m_lo = -1e30f, m_hi = -1e30f, l_lo = 0.0f, l_hi = 0.0f;

    float s[16][4];

    auto compute_S = [&](int stage) {
        const uint32_t kb = sbase + QSZ + stage * KSZ;
#pragma unroll
        for (int ntl = 0; ntl < 16; ntl++)
#pragma unroll
            for (int r = 0; r < 4; r++) s[ntl][r] = 0.0f;
#pragma unroll
        for (int kk = 0; kk < 8; kk++) {
            uint32_t af[4];
            ldsm4(af, swz(qB, qrow, kk * 2 + qhi));
#pragma unroll
            for (int np = 0; np < 8; np++) {
                uint32_t bf[4];
                ldsm4(bf, swz(kb, np * 16 + krow, kk * 2 + khi));
                mma16816(s[2 * np],     af, &bf[0]);
                mma16816(s[2 * np + 1], af, &bf[2]);
            }
        }
    };

    compute_S(0);

    for (int it = 0; it < nt; it++) {
        // ---- softmax(it) ----
        if (it == nt - 1) {
#pragma unroll
            for (int ntl = 0; ntl < 16; ntl++) {
#pragma unroll
                for (int c = 0; c < 2; c++) {
                    int key = it * 128 + ntl * 8 + (lane & 3) * 2 + c;
                    if (key > r_lo) s[ntl][c]     = -1e30f;
                    if (key > r_hi) s[ntl][2 + c] = -1e30f;
                }
            }
        }
        float mx_lo = -1e30f, mx_hi = -1e30f;
#pragma unroll
        for (int ntl = 0; ntl < 16; ntl++) {
            mx_lo = fmaxf(mx_lo, fmaxf(s[ntl][0], s[ntl][1]));
            mx_hi = fmaxf(mx_hi, fmaxf(s[ntl][2], s[ntl][3]));
        }
        mx_lo = fmaxf(mx_lo, __shfl_xor_sync(0xffffffffu, mx_lo, 1));
        mx_lo = fmaxf(mx_lo, __shfl_xor_sync(0xffffffffu, mx_lo, 2));
        mx_hi = fmaxf(mx_hi, __shfl_xor_sync(0xffffffffu, mx_hi, 1));
        mx_hi = fmaxf(mx_hi, __shfl_xor_sync(0xffffffffu, mx_hi, 2));
        float mn_lo = fmaxf(m_lo, mx_lo);
        float mn_hi = fmaxf(m_hi, mx_hi);
        float cr_lo = exp2f(m_lo - mn_lo);
        float cr_hi = exp2f(m_hi - mn_hi);
        m_lo = mn_lo; m_hi = mn_hi;

        uint32_t p2[16][2];
        float sum_lo = 0.0f, sum_hi = 0.0f;
#pragma unroll
        for (int ntl = 0; ntl < 16; ntl++) {
            float p0 = exp2f(s[ntl][0] - m_lo);
            float p1 = exp2f(s[ntl][1] - m_lo);
            float pc = exp2f(s[ntl][2] - m_hi);
            float p3 = exp2f(s[ntl][3] - m_hi);
            sum_lo += p0 + p1;
            sum_hi += pc + p3;
            p2[ntl][0] = packh2(p0, p1);
            p2[ntl][1] = packh2(pc, p3);
        }
        bool need = (cr_lo != 1.0f) || (cr_hi != 1.0f);
        if (__any_sync(0xffffffffu, need)) {
            l_lo = l_lo * cr_lo + sum_lo;
            l_hi = l_hi * cr_hi + sum_hi;
#pragma unroll
            for (int ntl = 0; ntl < 16; ntl++) {
                o[ntl][0] *= cr_lo; o[ntl][1] *= cr_lo;
                o[ntl][2] *= cr_hi; o[ntl][3] *= cr_hi;
            }
        } else {
            l_lo += sum_lo;
            l_hi += sum_hi;
        }

        // ---- V(it), K(it+1) guaranteed resident ----
        asm volatile("cp.async.wait_group 0;" ::: "memory");
        __syncthreads();

        // ---- PV(it) ----
#pragma unroll
        for (int kk = 0; kk < 8; kk++) {
            uint32_t pa[4] = {p2[2 * kk][0], p2[2 * kk][1],
                              p2[2 * kk + 1][0], p2[2 * kk + 1][1]};
#pragma unroll
            for (int nd = 0; nd < 8; nd++) {
                uint32_t vf[4];
                ldsm4t(vf, swz(vB, kk * 16 + vrow, nd * 2 + vhi));
                mma16816(o[2 * nd],     pa, &vf[0]);
                mma16816(o[2 * nd + 1], pa, &vf[2]);
            }
        }
        __syncthreads();                      // V buffer + K(it) stage free

        // ---- prefetch {V(it+1), K(it+2)}; then S(it+1) ----
        if (it + 1 < nt) {
            load_v((it + 1) * 128);
            if (it + 2 < nt) load_k(it & 1, (it + 2) * 128);
            asm volatile("cp.async.commit_group;" ::: "memory");
            compute_S((it + 1) & 1);
        }
    }

    // ---- epilogue ----
    l_lo += __shfl_xor_sync(0xffffffffu, l_lo, 1);
    l_lo += __shfl_xor_sync(0xffffffffu, l_lo, 2);
    l_hi += __shfl_xor_sync(0xffffffffu, l_hi, 1);
    l_hi += __shfl_xor_sync(0xffffffffu, l_hi, 2);
    const float inv_lo = 1.0f / l_lo;
    const float inv_hi = 1.0f / l_hi;
#pragma unroll
    for (int ntl = 0; ntl < 16; ntl++) {
        int col = h * D + ntl * 8 + (lane & 3) * 2;
        *(uint32_t*)&g_atf[(size_t)r_lo * QD + col] =
            packh2(o[ntl][0] * inv_lo, o[ntl][1] * inv_lo);
        *(uint32_t*)&g_atf[(size_t)r_hi * QD + col] =
            packh2(o[ntl][2] * inv_hi, o[ntl][3] * inv_hi);
    }
}

// ---------------------------------------------------------------------------
// Launch
// ---------------------------------------------------------------------------
extern "C" void kernel_launch(void* const* d_in, const int* in_sizes, int n_in,
                              void* d_out, int out_size) {
    const int*   positions = (const int*)d_in[0];
    const float* hs        = (const float*)d_in[1];
    const float* w_qkv     = (const float*)d_in[2];
    const float* w_o       = (const float*)d_in[3];
    const float* qnw       = (const float*)d_in[4];
    const float* knw       = (const float*)d_in[5];
    float*       out       = (float*)d_out;

    __half *qkvh, *hsf, *wqf, *wof, *atf;
    cudaGetSymbolAddress((void**)&qkvh, g_qkvh);
    cudaGetSymbolAddress((void**)&hsf, g_hsf);
    cudaGetSymbolAddress((void**)&wqf, g_wqf);
    cudaGetSymbolAddress((void**)&wof, g_wof);
    cudaGetSymbolAddress((void**)&atf, g_atf);

    static bool attr_set = false;
    if (!attr_set) {
        cudaFuncSetAttribute(gemm_hmma<true>,
                             cudaFuncAttributeMaxDynamicSharedMemorySize, GSMEM);
        cudaFuncSetAttribute(gemm_hmma<false>,
                             cudaFuncAttributeMaxDynamicSharedMemorySize, GSMEM);
        cudaFuncSetAttribute(flash_mma,
                             cudaFuncAttributeMaxDynamicSharedMemorySize, FSMEM);
        attr_set = true;
    }

    // 1) fused fp32->fp16 conversions
    cvt_f16<<<(N_HS + N_WQ + N_WO) / 1024, 256>>>(hs, w_qkv, w_o);
    // 2) QKV projection (fp16 output)
    {
        dim3 grid(QKV_N / 128, T / 128);
        gemm_hmma<true><<<grid, 256, GSMEM>>>(hsf, wqf, qkvh, QKV_N);
    }
    // 3) RoPE + RMSNorm (reads fp16 qkv)
    rope_norm_kernel<<<T, 256>>>(positions, qnw, knw);
    // 4) Causal GQA attention (128-key tiles, 2 CTAs/SM)
    {
        dim3 grid(T / 64, H);
        flash_mma<<<grid, 128, FSMEM>>>();
    }
    // 5) Output projection (fp32 output)
    {
        dim3 grid(HID / 128, T / 128);
        gemm_hmma<false><<<grid, 256, GSMEM>>>(atf, wof, out, HID);
    }
}

// round 12
// speedup vs baseline: 1.2461x; 1.0712x over previous
#include <cuda_runtime.h>
#include <cuda_fp16.h>
#include <math.h>
#include <stdint.h>

#define T     4096
#define H     16
#define HKV   4
#define D     128
#define HID   2048
#define QKV_N ((H + 2 * HKV) * D)   // 3072
#define QD    (H * D)               // 2048
#define KD    (HKV * D)             // 512
#define EPSV  1e-5f
#define GK    2048
#define GCH   64
#define NCH   (GK / GCH)            // 32 chunks

// fp16 scratch
__device__ __half g_qkvh[T * QKV_N];   // QKV projection output (fp16)
__device__ __half g_hsf[T * HID];
__device__ __half g_wqf[QKV_N * HID];
__device__ __half g_wof[HID * QD];
__device__ __half g_qf[T * QD];
__device__ __half g_kf[T * KD];
__device__ __half g_atf[T * QD];

// ---------------------------------------------------------------------------
// helpers (sm_80-level PTX only)
// ---------------------------------------------------------------------------
__device__ __forceinline__ uint32_t smem_u32(const void* p) {
    uint32_t a;
    asm("{ .reg .u64 t; cvta.to.shared.u64 t, %1; cvt.u32.u64 %0, t; }"
        : "=r"(a) : "l"(p));
    return a;
}
__device__ __forceinline__ void cp16(uint32_t dst, const void* src) {
    asm volatile("cp.async.cg.shared.global [%0], [%1], 16;"
                 :: "r"(dst), "l"(src));
}
__device__ __forceinline__ void ldsm4(uint32_t* r, uint32_t addr) {
    asm volatile("ldmatrix.sync.aligned.m8n8.x4.shared.b16 {%0,%1,%2,%3}, [%4];"
                 : "=r"(r[0]), "=r"(r[1]), "=r"(r[2]), "=r"(r[3]) : "r"(addr));
}
__device__ __forceinline__ void ldsm4t(uint32_t* r, uint32_t addr) {
    asm volatile("ldmatrix.sync.aligned.m8n8.x4.trans.shared.b16 {%0,%1,%2,%3}, [%4];"
                 : "=r"(r[0]), "=r"(r[1]), "=r"(r[2]), "=r"(r[3]) : "r"(addr));
}
__device__ __forceinline__ void ldsm2(uint32_t* r, uint32_t addr) {
    asm volatile("ldmatrix.sync.aligned.m8n8.x2.shared.b16 {%0,%1}, [%2];"
                 : "=r"(r[0]), "=r"(r[1]) : "r"(addr));
}
__device__ __forceinline__ void mma16816(float* c, const uint32_t* a,
                                         const uint32_t* b) {
    asm volatile(
        "mma.sync.aligned.m16n8k16.row.col.f32.f16.f16.f32 "
        "{%0,%1,%2,%3}, {%4,%5,%6,%7}, {%8,%9}, {%0,%1,%2,%3};"
        : "+f"(c[0]), "+f"(c[1]), "+f"(c[2]), "+f"(c[3])
        : "r"(a[0]), "r"(a[1]), "r"(a[2]), "r"(a[3]), "r"(b[0]), "r"(b[1]));
}
__device__ __forceinline__ uint32_t packh2(float a, float b) {
    __half2 h = __floats2half2_rn(a, b);
    return *(uint32_t*)&h;
}
// 256B rows, 16B-granular XOR swizzle (flash buffers)
__device__ __forceinline__ uint32_t swz(uint32_t base, int row, int col16) {
    return base + row * 256 + ((col16 ^ (row & 7)) << 4);
}

// ---------------------------------------------------------------------------
// fused fp32 -> fp16 conversion (vectorized, 1 launch)
// ---------------------------------------------------------------------------
#define N_HS  (T * HID)
#define N_WQ  (QKV_N * HID)
#define N_WO  (HID * QD)

__global__ __launch_bounds__(256) void cvt_f16(const float* __restrict__ hs,
                                               const float* __restrict__ wq,
                                               const float* __restrict__ wo) {
    long idx = ((long)blockIdx.x * 256 + threadIdx.x) * 4;
    const float* src;
    __half* dst;
    long off;
    if (idx < N_HS)             { src = hs; dst = g_hsf; off = idx; }
    else if (idx < N_HS + N_WQ) { src = wq; dst = g_wqf; off = idx - N_HS; }
    else                        { src = wo; dst = g_wof; off = idx - N_HS - N_WQ; }
    float4 v = *(const float4*)(src + off);
    uint2 w = make_uint2(packh2(v.x, v.y), packh2(v.z, v.w));
    *(uint2*)(dst + off) = w;
}

// ---------------------------------------------------------------------------
// mma.sync fp16 NT GEMM, BK=64 (32 chunks, 64 mma/warp/chunk), single
// barrier per chunk, 3-stage pipeline, 2 CTAs/SM. 144B smem rows:
// ldsm slot = row*9+off mod 8 = row+off mod 8 -> conflict-free.
// ---------------------------------------------------------------------------
#define TILE_B   (128 * 144)         // 18432 B per tile
#define STAGE_B  (2 * TILE_B)        // 36864 B (A + B)
#define GSMEM    (3 * STAGE_B)       // 110592 B

template<bool HALF_OUT>
__global__ __launch_bounds__(256, 2)
void gemm_hmma(const __half* __restrict__ A,
               const __half* __restrict__ B,
               void* __restrict__ Cv, int N) {
    extern __shared__ char smem[];
    const uint32_t sbase = smem_u32(smem);
    const int tid  = threadIdx.x;
    const int wid  = tid >> 5;
    const int lane = tid & 31;
    const int wm   = wid & 1;
    const int wn   = wid >> 1;
    const int bm   = blockIdx.y * 128;
    const int bn   = blockIdx.x * 128;

    const __half* srcs[2] = {A + (size_t)bm * GK, B + (size_t)bn * GK};

    auto load_chunk = [&](int stage, int k0) {
        uint32_t db = sbase + stage * STAGE_B;
#pragma unroll
        for (int t = 0; t < 2; t++) {
            const __half* s = srcs[t] + k0;
#pragma unroll
            for (int i = 0; i < 4; i++) {
                int seg = i * 256 + tid;            // 0..1023
                int row = seg >> 3, c16 = seg & 7;
                cp16(db + t * TILE_B + row * 144 + c16 * 16,
                     s + (size_t)row * GK + c16 * 8);
            }
        }
        asm volatile("cp.async.commit_group;" ::: "memory");
    };

    float acc[4][4][4];
#pragma unroll
    for (int mt = 0; mt < 4; mt++)
#pragma unroll
        for (int nt = 0; nt < 4; nt++)
#pragma unroll
            for (int r = 0; r < 4; r++) acc[mt][nt][r] = 0.0f;

    load_chunk(0, 0);
    load_chunk(1, GCH);

    const int arow  = lane & 15;
    const int akoff = (lane >> 4) * 16;
    const int brow  = lane & 7;
    const int bkoff = ((lane >> 3) & 1) * 16;

    for (int i = 0; i < NCH; i++) {
        if (i + 1 < NCH)
            asm volatile("cp.async.wait_group 1;" ::: "memory");
        else
            asm volatile("cp.async.wait_group 0;" ::: "memory");
        __syncthreads();   // top-bar also proves all warps done with stage (i+2)%3
        if (i + 2 < NCH) load_chunk((i + 2) % 3, (i + 2) * GCH);

        uint32_t s0 = sbase + (i % 3) * STAGE_B;
        uint32_t aB = s0, bB = s0 + TILE_B;

#pragma unroll
        for (int kk = 0; kk < 4; kk++) {
            const int kb = kk * 32;
            uint32_t af[4][4], bf[4][2];
#pragma unroll
            for (int mt = 0; mt < 4; mt++)
                ldsm4(af[mt], aB + (uint32_t)((wm * 64 + mt * 16 + arow) * 144 + kb + akoff));
#pragma unroll
            for (int nt = 0; nt < 4; nt++)
                ldsm2(bf[nt], bB + (uint32_t)((wn * 32 + nt * 8 + brow) * 144 + kb + bkoff));
#pragma unroll
            for (int mt = 0; mt < 4; mt++)
#pragma unroll
                for (int nt = 0; nt < 4; nt++)
                    mma16816(acc[mt][nt], af[mt], bf[nt]);
        }
    }

#pragma unroll
    for (int mt = 0; mt < 4; mt++) {
        const int row0 = bm + wm * 64 + mt * 16 + (lane >> 2);
#pragma unroll
        for (int nt = 0; nt < 4; nt++) {
            const int col = bn + wn * 32 + nt * 8 + (lane & 3) * 2;
            if (HALF_OUT) {
                __half* C = (__half*)Cv;
                *(uint32_t*)&C[(size_t)row0 * N + col] =
                    packh2(acc[mt][nt][0], acc[mt][nt][1]);
                *(uint32_t*)&C[(size_t)(row0 + 8) * N + col] =
                    packh2(acc[mt][nt][2], acc[mt][nt][3]);
            } else {
                float* C = (float*)Cv;
                *(float2*)&C[(size_t)row0 * N + col] =
                    make_float2(acc[mt][nt][0], acc[mt][nt][1]);
                *(float2*)&C[(size_t)(row0 + 8) * N + col] =
                    make_float2(acc[mt][nt][2], acc[mt][nt][3]);
            }
        }
    }
}

// ---------------------------------------------------------------------------
// RoPE + RMSNorm, reads fp16 qkv. Emits fp16 q (pre-scaled), k.
// ---------------------------------------------------------------------------
__global__ __launch_bounds__(256) void rope_norm_kernel(
    const int* __restrict__ positions,
    const float* __restrict__ qnw,
    const float* __restrict__ knw) {
    const int t    = blockIdx.x;
    const int tid  = threadIdx.x;
    const int lane = tid & 31;
    const float pos  = (float)positions[t];
    const float qpre = 0.08838834764831845f * 1.4426950408889634f;

    __shared__ float cs[64], sn[64];
    __shared__ float red[8];

    if (tid < 64) {
        float inv = powf(10000.0f, -(float)(2 * tid) * (1.0f / 128.0f));
        sincosf(pos * inv, &sn[tid], &cs[tid]);
    }
    __syncthreads();

    const __half* base = g_qkvh + (size_t)t * QKV_N;

    const int head = tid >> 4;
    const int c4   = (tid & 15) * 4;
    float av[4], bv[4];
    {
        uint2 ar = *(const uint2*)(base + head * 128 + c4);
        uint2 br = *(const uint2*)(base + head * 128 + 64 + c4);
        __half2* ah = (__half2*)&ar;
        __half2* bh = (__half2*)&br;
        float2 a0 = __half22float2(ah[0]), a1 = __half22float2(ah[1]);
        float2 b0 = __half22float2(bh[0]), b1 = __half22float2(bh[1]);
        av[0] = a0.x; av[1] = a0.y; av[2] = a1.x; av[3] = a1.y;
        bv[0] = b0.x; bv[1] = b0.y; bv[2] = b1.x; bv[3] = b1.y;
    }
    float o1[4], o2[4];
    {
        float ss = 0.0f;
#pragma unroll
        for (int j = 0; j < 4; j++) {
            float cv = cs[c4 + j], sv = sn[c4 + j];
            o1[j] = av[j] * cv - bv[j] * sv;
            o2[j] = bv[j] * cv + av[j] * sv;
            ss += o1[j] * o1[j] + o2[j] * o2[j];
        }
#pragma unroll
        for (int off = 16; off; off >>= 1)
            ss += __shfl_xor_sync(0xffffffffu, ss, off);
        if (lane == 0) red[tid >> 5] = ss;
    }
    __syncthreads();
    {
        float tot = red[0] + red[1] + red[2] + red[3] +
                    red[4] + red[5] + red[6] + red[7];
        float qs = rsqrtf(tot * (1.0f / QD) + EPSV) * qpre;
        float4 w1 = *(const float4*)(qnw + head * 128 + c4);
        float4 w2 = *(const float4*)(qnw + head * 128 + 64 + c4);
        __half* dst = g_qf + (size_t)t * QD + head * 128 + c4;
        *(uint2*)dst = make_uint2(packh2(o1[0] * qs * w1.x, o1[1] * qs * w1.y),
                                  packh2(o1[2] * qs * w1.z, o1[3] * qs * w1.w));
        *(uint2*)(dst + 64) = make_uint2(packh2(o2[0] * qs * w2.x, o2[1] * qs * w2.y),
                                         packh2(o2[2] * qs * w2.z, o2[3] * qs * w2.w));
    }
    __syncthreads();

    const int khead = tid >> 6;
    const int fi    = tid & 63;
    const __half* kp = base + QD + khead * 128 + fi;
    float k1, k2;
    {
        float ka = __half2float(kp[0]), kb = __half2float(kp[64]);
        float cv = cs[fi], sv = sn[fi];
        k1 = ka * cv - kb * sv;
        k2 = kb * cv + ka * sv;
        float ss = k1 * k1 + k2 * k2;
#pragma unroll
        for (int off = 16; off; off >>= 1)
            ss += __shfl_xor_sync(0xffffffffu, ss, off);
        if (lane == 0) red[tid >> 5] = ss;
    }
    __syncthreads();
    {
        float tot = red[0] + red[1] + red[2] + red[3] +
                    red[4] + red[5] + red[6] + red[7];
        float ks = rsqrtf(tot * (1.0f / KD) + EPSV);
        __half* dst = g_kf + (size_t)t * KD + khead * 128 + fi;
        dst[0]  = __float2half_rn(k1 * ks * knw[khead * 128 + fi]);
        dst[64] = __float2half_rn(k2 * ks * knw[khead * 128 + 64 + fi]);
    }
    // V: consumed directly from g_qkvh by flash (no copy)
}

// ---------------------------------------------------------------------------
// flash_mma: causal GQA attention, fp16 mma, software-pipelined.
// CTA: 64 queries x 1 head, 4 warps, 128-key tiles, 2 CTAs/SM.
// K double-buffered, V single-buffered. K(it+2) committed right after the
// post-softmax barrier (stage it&1 provably free there); V(it+1) committed
// after the post-PV barrier, a full S+softmax window before its use.
// ---------------------------------------------------------------------------
#define QSZ     16384                      // 64 rows x 256 B
#define KSZ     32768                      // 128 rows x 256 B
#define VSZ     32768
#define FSMEM   (QSZ + 2 * KSZ + VSZ)      // 114688 -> 2 CTAs/SM

__global__ __launch_bounds__(128, 2) void flash_mma() {
    extern __shared__ char smem[];
    const uint32_t sbase = smem_u32(smem);
    const int tid  = threadIdx.x;
    const int wg   = tid >> 5;
    const int lane = tid & 31;
    const int h    = blockIdx.y;
    const int kvh  = h >> 2;
    const int qb   = (int)gridDim.x - 1 - (int)blockIdx.x;
    const int q0   = qb * 64;
    const int nt   = qb / 2 + 1;           // 128-key tiles covering [0, q0+64)

    const uint32_t qB = sbase;
    const uint32_t vB = sbase + QSZ + 2 * KSZ;

    auto load_k = [&](int stage, int k0) {
        const __half* ks = g_kf + (size_t)k0 * KD + kvh * D;
        uint32_t kb = sbase + QSZ + stage * KSZ;
#pragma unroll
        for (int i = 0; i < 16; i++) {
            int seg = i * 128 + tid;           // 0..2047
            int row = seg >> 4, c = seg & 15;
            cp16(swz(kb, row, c), ks + (size_t)row * KD + c * 8);
        }
    };
    auto load_v = [&](int k0) {
        const __half* vs = g_qkvh + (size_t)k0 * QKV_N + QD + KD + kvh * D;
#pragma unroll
        for (int i = 0; i < 16; i++) {
            int seg = i * 128 + tid;
            int row = seg >> 4, c = seg & 15;
            cp16(swz(vB, row, c), vs + (size_t)row * QKV_N + c * 8);
        }
    };

    // ---- prologue: {Q, K0, V0} then {K1} ----
    {
        const __half* qs = g_qf + (size_t)q0 * QD + h * D;
#pragma unroll
        for (int i = 0; i < 8; i++) {
            int seg = i * 128 + tid;           // 0..1023
            int row = seg >> 4, c = seg & 15;
            cp16(swz(qB, row, c), qs + (size_t)row * QD + c * 8);
        }
        load_k(0, 0);
        load_v(0);
        asm volatile("cp.async.commit_group;" ::: "memory");
    }
    if (nt > 1) {
        load_k(1, 128);
        asm volatile("cp.async.commit_group;" ::: "memory");
        asm volatile("cp.async.wait_group 1;" ::: "memory");
    } else {
        asm volatile("cp.async.wait_group 0;" ::: "memory");
    }
    __syncthreads();

    // per-lane fragment coordinates
    const int qrow = wg * 16 + (lane & 15);
    const int qhi  = lane >> 4;
    const int krow = ((lane >> 4) << 3) + (lane & 7);
    const int khi  = (lane >> 3) & 1;
    const int vrow = (((lane >> 3) & 1) << 3) + (lane & 7);
    const int vhi  = lane >> 4;
    const int r_lo = q0 + wg * 16 + (lane >> 2);
    const int r_hi = r_lo + 8;

    float o[16][4];
#pragma unroll
    for (int ntl = 0; ntl < 16; ntl++)
#pragma unroll
        for (int r = 0; r < 4; r++) o[ntl][r] = 0.0f;
    float m_lo = -1e30f, m_hi = -1e30f, l_lo = 0.0f, l_hi = 0.0f;

    float s[16][4];

    auto compute_S = [&](int stage) {
        const uint32_t kb = sbase + QSZ + stage * KSZ;
#pragma unroll
        for (int ntl = 0; ntl < 16; ntl++)
#pragma unroll
            for (int r = 0; r < 4; r++) s[ntl][r] = 0.0f;
#pragma unroll
        for (int kk = 0; kk < 8; kk++) {
            uint32_t af[4];
            ldsm4(af, swz(qB, qrow, kk * 2 + qhi));
#pragma unroll
            for (int np = 0; np < 8; np++) {
                uint32_t bf[4];
                ldsm4(bf, swz(kb, np * 16 + krow, kk * 2 + khi));
                mma16816(s[2 * np],     af, &bf[0]);
                mma16816(s[2 * np + 1], af, &bf[2]);
            }
        }
    };

    compute_S(0);

    for (int it = 0; it < nt; it++) {
        // ---- softmax(it) ----
        if (it == nt - 1) {
#pragma unroll
            for (int ntl = 0; ntl < 16; ntl++) {
#pragma unroll
                for (int c = 0; c < 2; c++) {
                    int key = it * 128 + ntl * 8 + (lane & 3) * 2 + c;
                    if (key > r_lo) s[ntl][c]     = -1e30f;
                    if (key > r_hi) s[ntl][2 + c] = -1e30f;
                }
            }
        }
        float mx_lo = -1e30f, mx_hi = -1e30f;
#pragma unroll
        for (int ntl = 0; ntl < 16; ntl++) {
            mx_lo = fmaxf(mx_lo, fmaxf(s[ntl][0], s[ntl][1]));
            mx_hi = fmaxf(mx_hi, fmaxf(s[ntl][2], s[ntl][3]));
        }
        mx_lo = fmaxf(mx_lo, __shfl_xor_sync(0xffffffffu, mx_lo, 1));
        mx_lo = fmaxf(mx_lo, __shfl_xor_sync(0xffffffffu, mx_lo, 2));
        mx_hi = fmaxf(mx_hi, __shfl_xor_sync(0xffffffffu, mx_hi, 1));
        mx_hi = fmaxf(mx_hi, __shfl_xor_sync(0xffffffffu, mx_hi, 2));
        float mn_lo = fmaxf(m_lo, mx_lo);
        float mn_hi = fmaxf(m_hi, mx_hi);
        float cr_lo = exp2f(m_lo - mn_lo);
        float cr_hi = exp2f(m_hi - mn_hi);
        m_lo = mn_lo; m_hi = mn_hi;

        uint32_t p2[16][2];
        float sum_lo = 0.0f, sum_hi = 0.0f;
#pragma unroll
        for (int ntl = 0; ntl < 16; ntl++) {
            float p0 = exp2f(s[ntl][0] - m_lo);
            float p1 = exp2f(s[ntl][1] - m_lo);
            float pc = exp2f(s[ntl][2] - m_hi);
            float p3 = exp2f(s[ntl][3] - m_hi);
            sum_lo += p0 + p1;
            sum_hi += pc + p3;
            p2[ntl][0] = packh2(p0, p1);
            p2[ntl][1] = packh2(pc, p3);
        }
        bool need = (cr_lo != 1.0f) || (cr_hi != 1.0f);
        if (__any_sync(0xffffffffu, need)) {
            l_lo = l_lo * cr_lo + sum_lo;
            l_hi = l_hi * cr_hi + sum_hi;
#pragma unroll
            for (int ntl = 0; ntl < 16; ntl++) {
                o[ntl][0] *= cr_lo; o[ntl][1] *= cr_lo;
                o[ntl][2] *= cr_hi; o[ntl][3] *= cr_hi;
            }
        } else {
            l_lo += sum_lo;
            l_hi += sum_hi;
        }

        // ---- V(it) resident (K group committed separately) ----
        asm volatile("cp.async.wait_group 0;" ::: "memory");
        __syncthreads();

        // ---- K(it+2) commit: stage it&1 free (all warps ran S(it) pre-bar) ----
        if (it + 2 < nt) {
            load_k(it & 1, (it + 2) * 128);
            asm volatile("cp.async.commit_group;" ::: "memory");
        }

        // ---- PV(it) ----
#pragma unroll
        for (int kk = 0; kk < 8; kk++) {
            uint32_t pa[4] = {p2[2 * kk][0], p2[2 * kk][1],
                              p2[2 * kk + 1][0], p2[2 * kk + 1][1]};
#pragma unroll
            for (int nd = 0; nd < 8; nd++) {
                uint32_t vf[4];
                ldsm4t(vf, swz(vB, kk * 16 + vrow, nd * 2 + vhi));
                mma16816(o[2 * nd],     pa, &vf[0]);
                mma16816(o[2 * nd + 1], pa, &vf[2]);
            }
        }
        __syncthreads();                      // V buffer free

        // ---- V(it+1) commit, then S(it+1) (full window before V use) ----
        if (it + 1 < nt) {
            load_v((it + 1) * 128);
            asm volatile("cp.async.commit_group;" ::: "memory");
            compute_S((it + 1) & 1);
        }
    }

    // ---- epilogue ----
    l_lo += __shfl_xor_sync(0xffffffffu, l_lo, 1);
    l_lo += __shfl_xor_sync(0xffffffffu, l_lo, 2);
    l_hi += __shfl_xor_sync(0xffffffffu, l_hi, 1);
    l_hi += __shfl_xor_sync(0xffffffffu, l_hi, 2);
    const float inv_lo = 1.0f / l_lo;
    const float inv_hi = 1.0f / l_hi;
#pragma unroll
    for (int ntl = 0; ntl < 16; ntl++) {
        int col = h * D + ntl * 8 + (lane & 3) * 2;
        *(uint32_t*)&g_atf[(size_t)r_lo * QD + col] =
            packh2(o[ntl][0] * inv_lo, o[ntl][1] * inv_lo);
        *(uint32_t*)&g_atf[(size_t)r_hi * QD + col] =
            packh2(o[ntl][2] * inv_hi, o[ntl][3] * inv_hi);
    }
}

// ---------------------------------------------------------------------------
// Launch
// ---------------------------------------------------------------------------
extern "C" void kernel_launch(void* const* d_in, const int* in_sizes, int n_in,
                              void* d_out, int out_size) {
    const int*   positions = (const int*)d_in[0];
    const float* hs        = (const float*)d_in[1];
    const float* w_qkv     = (const float*)d_in[2];
    const float* w_o       = (const float*)d_in[3];
    const float* qnw       = (const float*)d_in[4];
    const float* knw       = (const float*)d_in[5];
    float*       out       = (float*)d_out;

    __half *qkvh, *hsf, *wqf, *wof, *atf;
    cudaGetSymbolAddress((void**)&qkvh, g_qkvh);
    cudaGetSymbolAddress((void**)&hsf, g_hsf);
    cudaGetSymbolAddress((void**)&wqf, g_wqf);
    cudaGetSymbolAddress((void**)&wof, g_wof);
    cudaGetSymbolAddress((void**)&atf, g_atf);

    static bool attr_set = false;
    if (!attr_set) {
        cudaFuncSetAttribute(gemm_hmma<true>,
                             cudaFuncAttributeMaxDynamicSharedMemorySize, GSMEM);
        cudaFuncSetAttribute(gemm_hmma<false>,
                             cudaFuncAttributeMaxDynamicSharedMemorySize, GSMEM);
        cudaFuncSetAttribute(flash_mma,
                             cudaFuncAttributeMaxDynamicSharedMemorySize, FSMEM);
        attr_set = true;
    }

    // 1) fused fp32->fp16 conversions
    cvt_f16<<<(N_HS + N_WQ + N_WO) / 1024, 256>>>(hs, w_qkv, w_o);
    // 2) QKV projection (fp16 output)
    {
        dim3 grid(QKV_N / 128, T / 128);
        gemm_hmma<true><<<grid, 256, GSMEM>>>(hsf, wqf, qkvh, QKV_N);
    }
    // 3) RoPE + RMSNorm (reads fp16 qkv)
    rope_norm_kernel<<<T, 256>>>(positions, qnw, knw);
    // 4) Causal GQA attention (128-key tiles, 2 CTAs/SM)
    {
        dim3 grid(T / 64, H);
        flash_mma<<<grid, 128, FSMEM>>>();
    }
    // 5) Output projection (fp32 output)
    {
        dim3 grid(HID / 128, T / 128);
        gemm_hmma<false><<<grid, 256, GSMEM>>>(atf, wof, out, HID);
    }
}